// round 2
// baseline (speedup 1.0000x reference)
#include <cuda_runtime.h>
#include <math.h>

// ---------------- problem constants ----------------
#define GB   2
#define GS   2048
#define GD   4096
#define GH   32          // query heads
#define GKH  8           // kv heads
#define GHD  128         // head dim
#define QKV_OUT 6144     // (32 + 2*8) * 128

// ---------------- device scratch (no allocations allowed) ----------------
__device__ float g_qkv[GB*GS*QKV_OUT];   // 4096 x 6144 (~100MB)
__device__ float g_attn[GB*GS*GD];       // 4096 x 4096 (~64MB)

// ---------------- packed f32x2 helpers (Blackwell FFMA2 via PTX) ----------------
__device__ __forceinline__ unsigned long long pk2(float lo, float hi){
    unsigned long long r;
    asm("mov.b64 %0, {%1, %2};" : "=l"(r) : "f"(lo), "f"(hi));
    return r;
}
__device__ __forceinline__ void fma2(unsigned long long& d, unsigned long long a, unsigned long long b){
    asm("fma.rn.f32x2 %0, %1, %2, %0;" : "+l"(d) : "l"(a), "l"(b));
}
__device__ __forceinline__ float2 up2(unsigned long long v){
    float2 f;
    asm("mov.b64 {%0, %1}, %2;" : "=f"(f.x), "=f"(f.y) : "l"(v));
    return f;
}

// ---------------- NT GEMM: C[M,N] = A[M,K] * B[N,K]^T (all row-major) ----------------
#define BM 128
#define BN 128
#define BK 16

__device__ __forceinline__ void gemm_nt_body(
    const float* __restrict__ A, const float* __restrict__ B, float* __restrict__ C,
    int N, int K)
{
    __shared__ __align__(16) float As[BK][BM+4];
    __shared__ __align__(16) float Bs[BK][BN+4];

    const int tid = threadIdx.x;          // 256 threads
    const int tr  = tid >> 4;             // 0..15 (m micro-tile)
    const int tc  = tid & 15;             // 0..15 (n micro-tile)
    const int m0  = blockIdx.y * BM;
    const int n0  = blockIdx.x * BN;
    const int lr  = tid >> 2;             // 0..63 loader row
    const int lc  = (tid & 3) << 2;       // 0,4,8,12 loader col (float4)

    unsigned long long acc[8][4];
    #pragma unroll
    for (int i=0;i<8;i++)
        #pragma unroll
        for (int j=0;j<4;j++) acc[i][j] = 0ULL;

    for (int k0 = 0; k0 < K; k0 += BK) {
        #pragma unroll
        for (int h = 0; h < 2; ++h) {
            const int row = lr + h*64;
            const float4 a4 = *(const float4*)(A + (size_t)(m0+row)*K + k0 + lc);
            As[lc+0][row]=a4.x; As[lc+1][row]=a4.y; As[lc+2][row]=a4.z; As[lc+3][row]=a4.w;
            const float4 b4 = *(const float4*)(B + (size_t)(n0+row)*K + k0 + lc);
            Bs[lc+0][row]=b4.x; Bs[lc+1][row]=b4.y; Bs[lc+2][row]=b4.z; Bs[lc+3][row]=b4.w;
        }
        __syncthreads();

        #pragma unroll
        for (int k=0;k<BK;k++){
            const float4 a0 = *(const float4*)&As[k][tr*8];
            const float4 a1 = *(const float4*)&As[k][tr*8+4];
            const float4 b0 = *(const float4*)&Bs[k][tc*8];
            const float4 b1 = *(const float4*)&Bs[k][tc*8+4];
            unsigned long long bp[4];
            bp[0]=pk2(b0.x,b0.y); bp[1]=pk2(b0.z,b0.w);
            bp[2]=pk2(b1.x,b1.y); bp[3]=pk2(b1.z,b1.w);
            const float aa[8] = {a0.x,a0.y,a0.z,a0.w,a1.x,a1.y,a1.z,a1.w};
            #pragma unroll
            for (int i=0;i<8;i++){
                const unsigned long long ap = pk2(aa[i],aa[i]);
                #pragma unroll
                for (int j=0;j<4;j++) fma2(acc[i][j], ap, bp[j]);
            }
        }
        __syncthreads();
    }

    #pragma unroll
    for (int i=0;i<8;i++){
        const float2 p0=up2(acc[i][0]), p1=up2(acc[i][1]);
        const float2 p2=up2(acc[i][2]), p3=up2(acc[i][3]);
        const float4 v0 = make_float4(p0.x,p0.y,p1.x,p1.y);
        const float4 v1 = make_float4(p2.x,p2.y,p3.x,p3.y);
        float* cp = C + (size_t)(m0 + tr*8 + i)*N + n0 + tc*8;
        *(float4*)cp     = v0;
        *(float4*)(cp+4) = v1;
    }
}

__global__ __launch_bounds__(256) void gemm_qkv_kernel(const float* __restrict__ x,
                                                       const float* __restrict__ Wqkv){
    gemm_nt_body(x, Wqkv, g_qkv, QKV_OUT, GD);
}
__global__ __launch_bounds__(256) void gemm_out_kernel(const float* __restrict__ Wo,
                                                       float* __restrict__ out){
    gemm_nt_body(g_attn, Wo, out, GD, GD);
}

// ---------------- RoPE (in-place on q and k regions of g_qkv) ----------------
__global__ void rope_kernel(){
    const int row  = blockIdx.x;             // b*S + s
    const float fpos = (float)(row & (GS-1));
    float* base = g_qkv + (size_t)row * QKV_OUT;
    // 40 heads to rotate: 32 q heads + 8 k heads. 64 rotation pairs each.
    for (int it = threadIdx.x; it < 40*64; it += blockDim.x){
        const int hh = it >> 6;
        const int i  = it & 63;
        float* p = base + (hh < GH ? hh*GHD : GH*GHD + (hh-GH)*GHD);
        const float inv = powf(500000.0f, -(float)i * (1.0f/64.0f));
        const float fr  = fpos * inv;
        float sn, cs;
        sincosf(fr, &sn, &cs);
        const float x1 = p[i], x2 = p[i+64];
        p[i]    = x1*cs - x2*sn;
        p[i+64] = x2*cs + x1*sn;
    }
}

// ---------------- flash attention (fp32, causal, GQA 4:1) ----------------
#define QSTR 68  // padded smem stride for transposed Q/K (float4-aligned, low conflict)
#define ATT_SMEM ((2*128*QSTR + 64*128 + 64*64)*4)   // 118784 bytes

__global__ __launch_bounds__(256) void attn_kernel(){
    extern __shared__ __align__(16) float sm[];
    float* Qt = sm;                    // [128][QSTR]  (Q^T: d-major)
    float* Kt = sm + 128*QSTR;         // [128][QSTR]
    float* Vs = sm + 2*128*QSTR;       // [64][128]
    float* Ps = Vs + 64*128;           // [64][64]

    const int tid = threadIdx.x;
    const int ty  = tid >> 4;          // 0..15: 4 query rows each
    const int tx  = tid & 15;          // 0..15: 4 score cols / 8 out cols each
    const int qt  = blockIdx.x;        // query tile (64 rows)
    const int h   = blockIdx.y;
    const int b   = blockIdx.z;
    const int kh  = h >> 2;            // GQA: 4 q-heads per kv-head

    const float* qbase = g_qkv + (size_t)b*GS*QKV_OUT + h*GHD;
    const float* kbase = g_qkv + (size_t)b*GS*QKV_OUT + GH*GHD + kh*GHD;
    const float* vbase = kbase + GKH*GHD;

    // load Q tile transposed into smem
    for (int idx = tid; idx < 64*128; idx += 256){
        const int r = idx >> 7, d = idx & 127;
        Qt[d*QSTR + r] = qbase[(size_t)(qt*64 + r)*QKV_OUT + d];
    }

    float m[4], l[4], o[4][8];
    #pragma unroll
    for (int i=0;i<4;i++){
        m[i] = -1e30f; l[i] = 0.f;
        #pragma unroll
        for (int c=0;c<8;c++) o[i][c] = 0.f;
    }
    const float scale = 0.08838834764831845f;  // 1/sqrt(128)

    for (int kt = 0; kt <= qt; ++kt){
        __syncthreads();   // previous iteration done with Kt/Vs (also covers Qt on iter 0)
        for (int idx = tid; idx < 64*128; idx += 256){
            const int r = idx >> 7, d = idx & 127;
            const size_t grow = (size_t)(kt*64 + r)*QKV_OUT + d;
            Kt[d*QSTR + r] = kbase[grow];
            Vs[idx]        = vbase[grow];
        }
        __syncthreads();

        // scores: S = Q K^T  (64x64, each thread 4x4)
        float s[4][4];
        #pragma unroll
        for (int i=0;i<4;i++)
            #pragma unroll
            for (int j=0;j<4;j++) s[i][j] = 0.f;

        #pragma unroll 4
        for (int d = 0; d < 128; ++d){
            const float4 q4 = *(const float4*)&Qt[d*QSTR + ty*4];
            const float4 k4 = *(const float4*)&Kt[d*QSTR + tx*4];
            const float qv[4] = {q4.x,q4.y,q4.z,q4.w};
            const float kv[4] = {k4.x,k4.y,k4.z,k4.w};
            #pragma unroll
            for (int i=0;i<4;i++)
                #pragma unroll
                for (int j=0;j<4;j++) s[i][j] += qv[i]*kv[j];
        }

        const bool diag = (kt == qt);
        #pragma unroll
        for (int i=0;i<4;i++){
            const int qrow = qt*64 + ty*4 + i;
            float sv[4]; float rm = -1e30f;
            #pragma unroll
            for (int j=0;j<4;j++){
                float v = s[i][j]*scale;
                if (diag && (kt*64 + tx*4 + j) > qrow) v = -1e30f;
                sv[j] = v; rm = fmaxf(rm, v);
            }
            #pragma unroll
            for (int off=8; off>0; off>>=1)
                rm = fmaxf(rm, __shfl_xor_sync(0xffffffffu, rm, off));
            const float mn    = fmaxf(m[i], rm);
            const float alpha = expf(m[i]-mn);
            float ps = 0.f;
            #pragma unroll
            for (int j=0;j<4;j++){
                const float p = expf(sv[j]-mn);
                ps += p;
                Ps[(ty*4+i)*64 + tx*4 + j] = p;
            }
            #pragma unroll
            for (int off=8; off>0; off>>=1)
                ps += __shfl_xor_sync(0xffffffffu, ps, off);
            l[i] = l[i]*alpha + ps;
            m[i] = mn;
            #pragma unroll
            for (int c=0;c<8;c++) o[i][c] *= alpha;
        }
        __syncthreads();

        // O += P V   (64x128, each thread 4 rows x 8 cols)
        #pragma unroll 2
        for (int kk=0; kk<64; ++kk){
            const float4 v0 = *(const float4*)&Vs[kk*128 + tx*8];
            const float4 v1 = *(const float4*)&Vs[kk*128 + tx*8 + 4];
            const float vv[8] = {v0.x,v0.y,v0.z,v0.w,v1.x,v1.y,v1.z,v1.w};
            #pragma unroll
            for (int i=0;i<4;i++){
                const float p = Ps[(ty*4+i)*64 + kk];
                #pragma unroll
                for (int c=0;c<8;c++) o[i][c] += p*vv[c];
            }
        }
    }

    // epilogue: O /= l, write [B, S, H*hd] so the out-proj GEMM reads rows directly
    #pragma unroll
    for (int i=0;i<4;i++){
        const int qrow = qt*64 + ty*4 + i;
        const float inv = 1.0f/l[i];
        float* op = g_attn + ((size_t)(b*GS + qrow))*GD + h*GHD + tx*8;
        const float4 w0 = make_float4(o[i][0]*inv,o[i][1]*inv,o[i][2]*inv,o[i][3]*inv);
        const float4 w1 = make_float4(o[i][4]*inv,o[i][5]*inv,o[i][6]*inv,o[i][7]*inv);
        *(float4*)op     = w0;
        *(float4*)(op+4) = w1;
    }
}

// ---------------- launch ----------------
extern "C" void kernel_launch(void* const* d_in, const int* in_sizes, int n_in,
                              void* d_out, int out_size)
{
    const float* x    = (const float*)d_in[0];   // [2,2048,4096]
    const float* Wqkv = (const float*)d_in[1];   // [6144,4096]
    const float* Wo   = (const float*)d_in[2];   // [4096,4096]
    float* out = (float*)d_out;                  // [2,2048,4096]

    cudaFuncSetAttribute(attn_kernel, cudaFuncAttributeMaxDynamicSharedMemorySize, ATT_SMEM);

    dim3 g1(QKV_OUT/BN, (GB*GS)/BM);
    gemm_qkv_kernel<<<g1, 256>>>(x, Wqkv);

    rope_kernel<<<GB*GS, 256>>>();

    dim3 ga(GS/64, GH, GB);
    attn_kernel<<<ga, 256, ATT_SMEM>>>();

    dim3 g2(GD/BN, (GB*GS)/BM);
    gemm_out_kernel<<<g2, 256>>>(Wo, out);
}

// round 4
// speedup vs baseline: 1.5673x; 1.5673x over previous
#include <cuda_runtime.h>
#include <cuda_bf16.h>
#include <math.h>
#include <stdint.h>

// ---------------- problem constants ----------------
#define GB   2
#define GS   2048
#define GD   4096
#define GH   32
#define GKH  8
#define GHD  128
#define QKV_OUT 6144

// ---------------- device scratch ----------------
__device__ float g_qkv[GB*GS*QKV_OUT];
__device__ float g_attn[GB*GS*GD];

// ---------------- f32x2 helpers ----------------
__device__ __forceinline__ unsigned long long pk2(float lo, float hi){
    unsigned long long r;
    asm("mov.b64 %0, {%1, %2};" : "=l"(r) : "f"(lo), "f"(hi));
    return r;
}
__device__ __forceinline__ void fma2(unsigned long long& d, unsigned long long a, unsigned long long b){
    asm("fma.rn.f32x2 %0, %1, %2, %0;" : "+l"(d) : "l"(a), "l"(b));
}
__device__ __forceinline__ void mul2(unsigned long long& d, unsigned long long a){
    asm("mul.rn.f32x2 %0, %1, %2;" : "=l"(d) : "l"(d), "l"(a));
}
__device__ __forceinline__ float2 up2(unsigned long long v){
    float2 f;
    asm("mov.b64 {%0, %1}, %2;" : "=f"(f.x), "=f"(f.y) : "l"(v));
    return f;
}

// ---------------- smem addr helper ----------------
__device__ __forceinline__ uint32_t smem_u32(const void* p){
    uint32_t a;
    asm("{ .reg .u64 t; cvta.to.shared.u64 t, %1; cvt.u32.u64 %0, t; }" : "=r"(a) : "l"(p));
    return a;
}

// ---------------- HMMA helpers (sm_80+ mma.sync, legal on bare sm_103 target) ----------------
__device__ __forceinline__ void ldmx4(uint32_t* r, uint32_t addr){
    asm volatile("ldmatrix.sync.aligned.m8n8.x4.shared.b16 {%0,%1,%2,%3}, [%4];"
        : "=r"(r[0]), "=r"(r[1]), "=r"(r[2]), "=r"(r[3]) : "r"(addr));
}
__device__ __forceinline__ void mma16816(float* c, const uint32_t* a, const uint32_t* b){
    asm volatile(
        "mma.sync.aligned.m16n8k16.row.col.f32.bf16.bf16.f32 "
        "{%0,%1,%2,%3}, {%4,%5,%6,%7}, {%8,%9}, {%0,%1,%2,%3};"
        : "+f"(c[0]), "+f"(c[1]), "+f"(c[2]), "+f"(c[3])
        : "r"(a[0]), "r"(a[1]), "r"(a[2]), "r"(a[3]), "r"(b[0]), "r"(b[1]));
}

// ---------------- hi/lo bf16 split of a float4 ----------------
__device__ __forceinline__ void hilo4(float4 v, unsigned long long& h, unsigned long long& l){
    __nv_bfloat16 h0 = __float2bfloat16(v.x);
    __nv_bfloat16 h1 = __float2bfloat16(v.y);
    __nv_bfloat16 h2 = __float2bfloat16(v.z);
    __nv_bfloat16 h3 = __float2bfloat16(v.w);
    __nv_bfloat16 l0 = __float2bfloat16(v.x - __bfloat162float(h0));
    __nv_bfloat16 l1 = __float2bfloat16(v.y - __bfloat162float(h1));
    __nv_bfloat16 l2 = __float2bfloat16(v.z - __bfloat162float(h2));
    __nv_bfloat16 l3 = __float2bfloat16(v.w - __bfloat162float(h3));
    h = (unsigned long long)__bfloat16_as_ushort(h0)
      | ((unsigned long long)__bfloat16_as_ushort(h1) << 16)
      | ((unsigned long long)__bfloat16_as_ushort(h2) << 32)
      | ((unsigned long long)__bfloat16_as_ushort(h3) << 48);
    l = (unsigned long long)__bfloat16_as_ushort(l0)
      | ((unsigned long long)__bfloat16_as_ushort(l1) << 16)
      | ((unsigned long long)__bfloat16_as_ushort(l2) << 32)
      | ((unsigned long long)__bfloat16_as_ushort(l3) << 48);
}

// ---------------- HMMA bf16x3 GEMM: C[M,N] = A[M,K] * B[N,K]^T ----------------
// CTA tile 128x128, BK=32 (bf16), 256 threads = 8 warps, warp tile 64x32.
// SMEM: 4 tiles (Ah,Al,Bh,Bl), pitch 40 bf16 (80B, conflict-free for ldmatrix),
// double buffered: 4 * 10240 * 2 = 81920 bytes dynamic.
#define GP   80            // row pitch bytes
#define TB   10240         // one tile bytes (128*80)
#define STG  (4*TB)        // one stage
#define GEMM_SMEM (2*STG)

__device__ __forceinline__ void gemm_mma_body(
    const float* __restrict__ A, const float* __restrict__ B, float* __restrict__ C,
    int N, int K)
{
    extern __shared__ __align__(16) char dyn[];
    const uint32_t sb = smem_u32(dyn);

    const int tid  = threadIdx.x;
    const int wid  = tid >> 5;
    const int lane = tid & 31;
    const int wm   = (wid & 1) * 64;    // warp m offset
    const int wn   = (wid >> 1) * 32;   // warp n offset
    const int m0   = blockIdx.y * 128;
    const int n0   = blockIdx.x * 128;

    float acc[4][4][4];
    #pragma unroll
    for (int i=0;i<4;i++)
        #pragma unroll
        for (int j=0;j<4;j++)
            #pragma unroll
            for (int c=0;c<4;c++) acc[i][j][c] = 0.f;

    // loader mapping: 1024 float4 per matrix per stage, 4 per thread
    const int lrow0 = tid >> 3;            // base row for p-loop: row = lrow0 + p*32? no:
    // idx = p*256 + tid; row = idx>>3; c4 = (idx&7)*4
    float4 ra[4], rb[4];

    auto loadG = [&](int k0){
        #pragma unroll
        for (int p=0;p<4;p++){
            const int idx = p*256 + tid;
            const int row = idx >> 3;
            const int c4  = (idx & 7) << 2;
            ra[p] = *(const float4*)(A + (size_t)(m0+row)*K + k0 + c4);
            rb[p] = *(const float4*)(B + (size_t)(n0+row)*K + k0 + c4);
        }
    };
    auto storeS = [&](int s){
        char* base = dyn + s*STG;
        #pragma unroll
        for (int p=0;p<4;p++){
            const int idx = p*256 + tid;
            const int row = idx >> 3;
            const int c4  = (idx & 7) << 2;
            const int off = row*GP + c4*2;
            unsigned long long h, l;
            hilo4(ra[p], h, l);
            *(unsigned long long*)(base + off)       = h;
            *(unsigned long long*)(base + TB + off)  = l;
            hilo4(rb[p], h, l);
            *(unsigned long long*)(base + 2*TB + off) = h;
            *(unsigned long long*)(base + 3*TB + off) = l;
        }
    };

    const int NIT = K / 32;
    loadG(0);
    storeS(0);
    __syncthreads();

    // precomputed lane pieces for ldmatrix addressing
    const int arow = wm + (lane & 15);             // + mi*16
    const int akb  = (lane >> 4) * 16;             // + ks*32
    const int brow = wn + (lane & 7) + ((lane >> 4) << 3);   // + n2*16
    const int bkb  = ((lane >> 3) & 1) * 16;       // + ks*32

    for (int it = 0; it < NIT; ++it){
        if (it + 1 < NIT) loadG((it+1)*32);

        const uint32_t stage = sb + (uint32_t)((it & 1) * STG);
        #pragma unroll
        for (int ks = 0; ks < 2; ++ks){
            uint32_t ah[4][4], al[4][4], bh[2][4], bl[2][4];
            #pragma unroll
            for (int mi = 0; mi < 4; ++mi){
                const uint32_t ad = stage + (uint32_t)((arow + mi*16)*GP + ks*32 + akb);
                ldmx4(ah[mi], ad);
                ldmx4(al[mi], ad + TB);
            }
            #pragma unroll
            for (int n2 = 0; n2 < 2; ++n2){
                const uint32_t bd = stage + (uint32_t)(2*TB + (brow + n2*16)*GP + ks*32 + bkb);
                ldmx4(bh[n2], bd);
                ldmx4(bl[n2], bd + TB);
            }
            #pragma unroll
            for (int mi = 0; mi < 4; ++mi)
                #pragma unroll
                for (int ni = 0; ni < 4; ++ni){
                    const uint32_t* bhp = &bh[ni>>1][(ni&1)*2];
                    const uint32_t* blp = &bl[ni>>1][(ni&1)*2];
                    mma16816(acc[mi][ni], ah[mi], bhp);
                    mma16816(acc[mi][ni], ah[mi], blp);
                    mma16816(acc[mi][ni], al[mi], bhp);
                }
        }
        __syncthreads();
        if (it + 1 < NIT){
            storeS((it+1) & 1);
            __syncthreads();
        }
    }

    // epilogue: direct fp32 stores (float2 per fragment half)
    const int erow = (lane >> 2);
    const int ecol = (lane & 3) * 2;
    #pragma unroll
    for (int mi = 0; mi < 4; ++mi){
        #pragma unroll
        for (int ni = 0; ni < 4; ++ni){
            const int gm = m0 + wm + mi*16 + erow;
            const int gn = n0 + wn + ni*8 + ecol;
            *(float2*)(C + (size_t)gm*N + gn)     = make_float2(acc[mi][ni][0], acc[mi][ni][1]);
            *(float2*)(C + (size_t)(gm+8)*N + gn) = make_float2(acc[mi][ni][2], acc[mi][ni][3]);
        }
    }
}

__global__ __launch_bounds__(256, 1) void gemm_mma_qkv(const float* __restrict__ x,
                                                       const float* __restrict__ Wqkv){
    gemm_mma_body(x, Wqkv, g_qkv, QKV_OUT, GD);
}
__global__ __launch_bounds__(256, 1) void gemm_mma_out(const float* __restrict__ Wo,
                                                       float* __restrict__ out){
    gemm_mma_body(g_attn, Wo, out, GD, GD);
}

// ---------------- RoPE ----------------
__global__ void rope_kernel(){
    const int row = blockIdx.x;
    const float fpos = (float)(row & (GS-1));
    float* base = g_qkv + (size_t)row * QKV_OUT;
    for (int it = threadIdx.x; it < 40*64; it += blockDim.x){
        const int hh = it >> 6;
        const int i  = it & 63;
        float* p = base + (hh < GH ? hh*GHD : GH*GHD + (hh-GH)*GHD);
        const float inv = powf(500000.0f, -(float)i * (1.0f/64.0f));
        const float fr  = fpos * inv;
        float sn, cs;
        sincosf(fr, &sn, &cs);
        const float x1 = p[i], x2 = p[i+64];
        p[i]    = x1*cs - x2*sn;
        p[i+64] = x2*cs + x1*sn;
    }
}

// ---------------- flash attention (fp32 + f32x2, causal, GQA 4:1) ----------------
#define QSTR 68
#define ATT_SMEM ((2*128*QSTR + 64*128 + 64*64)*4)

__global__ __launch_bounds__(256) void attn_kernel(){
    extern __shared__ __align__(16) float sm[];
    float* Qt = sm;                    // [128][QSTR]
    float* Kt = sm + 128*QSTR;         // [128][QSTR]
    float* Vs = sm + 2*128*QSTR;       // [64][128]
    float* Ps = Vs + 64*128;           // [64][64]

    const int tid = threadIdx.x;
    const int ty  = tid >> 4;
    const int tx  = tid & 15;
    const int qt  = blockIdx.x;
    const int h   = blockIdx.y;
    const int b   = blockIdx.z;
    const int kh  = h >> 2;

    const float* qbase = g_qkv + (size_t)b*GS*QKV_OUT + h*GHD;
    const float* kbase = g_qkv + (size_t)b*GS*QKV_OUT + GH*GHD + kh*GHD;
    const float* vbase = kbase + GKH*GHD;

    for (int idx = tid; idx < 64*128; idx += 256){
        const int r = idx >> 7, d = idx & 127;
        Qt[d*QSTR + r] = qbase[(size_t)(qt*64 + r)*QKV_OUT + d];
    }

    float m[4], l[4];
    unsigned long long o2[4][4];
    #pragma unroll
    for (int i = 0; i < 4; ++i){
        m[i] = -1e30f; l[i] = 0.f;
        #pragma unroll
        for (int c = 0; c < 4; ++c) o2[i][c] = 0ULL;
    }
    const float scale = 0.08838834764831845f;

    for (int kt = 0; kt <= qt; ++kt){
        __syncthreads();
        for (int idx = tid; idx < 64*128; idx += 256){
            const int r = idx >> 7, d = idx & 127;
            const size_t grow = (size_t)(kt*64 + r)*QKV_OUT + d;
            Kt[d*QSTR + r] = kbase[grow];
            Vs[idx]        = vbase[grow];
        }
        __syncthreads();

        unsigned long long s2[4][2];
        #pragma unroll
        for (int i = 0; i < 4; ++i){ s2[i][0] = 0ULL; s2[i][1] = 0ULL; }

        #pragma unroll 4
        for (int d = 0; d < 128; ++d){
            const float4 q4 = *(const float4*)&Qt[d*QSTR + ty*4];
            const float4 k4 = *(const float4*)&Kt[d*QSTR + tx*4];
            const unsigned long long kp0 = pk2(k4.x, k4.y);
            const unsigned long long kp1 = pk2(k4.z, k4.w);
            const float qv[4] = {q4.x, q4.y, q4.z, q4.w};
            #pragma unroll
            for (int i = 0; i < 4; ++i){
                const unsigned long long ap = pk2(qv[i], qv[i]);
                fma2(s2[i][0], ap, kp0);
                fma2(s2[i][1], ap, kp1);
            }
        }

        const bool diag = (kt == qt);
        #pragma unroll
        for (int i = 0; i < 4; ++i){
            const int qrow = qt*64 + ty*4 + i;
            const float2 pa = up2(s2[i][0]);
            const float2 pb = up2(s2[i][1]);
            float sv[4] = {pa.x, pa.y, pb.x, pb.y};
            float rm = -1e30f;
            #pragma unroll
            for (int j = 0; j < 4; ++j){
                float v = sv[j]*scale;
                if (diag && (kt*64 + tx*4 + j) > qrow) v = -1e30f;
                sv[j] = v; rm = fmaxf(rm, v);
            }
            #pragma unroll
            for (int off = 8; off > 0; off >>= 1)
                rm = fmaxf(rm, __shfl_xor_sync(0xffffffffu, rm, off));
            const float mn    = fmaxf(m[i], rm);
            const float alpha = expf(m[i] - mn);
            float ps = 0.f;
            #pragma unroll
            for (int j = 0; j < 4; ++j){
                const float p = expf(sv[j] - mn);
                ps += p;
                Ps[(ty*4+i)*64 + tx*4 + j] = p;
            }
            #pragma unroll
            for (int off = 8; off > 0; off >>= 1)
                ps += __shfl_xor_sync(0xffffffffu, ps, off);
            l[i] = l[i]*alpha + ps;
            m[i] = mn;
            const unsigned long long am = pk2(alpha, alpha);
            #pragma unroll
            for (int c = 0; c < 4; ++c) mul2(o2[i][c], am);
        }
        __syncthreads();

        #pragma unroll 2
        for (int kk = 0; kk < 64; ++kk){
            const float4 v0 = *(const float4*)&Vs[kk*128 + tx*8];
            const float4 v1 = *(const float4*)&Vs[kk*128 + tx*8 + 4];
            const unsigned long long vp[4] = {
                pk2(v0.x, v0.y), pk2(v0.z, v0.w), pk2(v1.x, v1.y), pk2(v1.z, v1.w)
            };
            #pragma unroll
            for (int i = 0; i < 4; ++i){
                const float p = Ps[(ty*4+i)*64 + kk];
                const unsigned long long pp = pk2(p, p);
                #pragma unroll
                for (int c = 0; c < 4; ++c) fma2(o2[i][c], pp, vp[c]);
            }
        }
    }

    #pragma unroll
    for (int i = 0; i < 4; ++i){
        const int qrow = qt*64 + ty*4 + i;
        const float inv = 1.0f / l[i];
        float* op = g_attn + ((size_t)(b*GS + qrow))*GD + h*GHD + tx*8;
        const float2 a0 = up2(o2[i][0]), a1 = up2(o2[i][1]);
        const float2 a2 = up2(o2[i][2]), a3 = up2(o2[i][3]);
        *(float4*)op     = make_float4(a0.x*inv, a0.y*inv, a1.x*inv, a1.y*inv);
        *(float4*)(op+4) = make_float4(a2.x*inv, a2.y*inv, a3.x*inv, a3.y*inv);
    }
}

// ---------------- launch ----------------
extern "C" void kernel_launch(void* const* d_in, const int* in_sizes, int n_in,
                              void* d_out, int out_size)
{
    const float* x    = (const float*)d_in[0];
    const float* Wqkv = (const float*)d_in[1];
    const float* Wo   = (const float*)d_in[2];
    float* out = (float*)d_out;

    cudaFuncSetAttribute(gemm_mma_qkv, cudaFuncAttributeMaxDynamicSharedMemorySize, GEMM_SMEM);
    cudaFuncSetAttribute(gemm_mma_out, cudaFuncAttributeMaxDynamicSharedMemorySize, GEMM_SMEM);
    cudaFuncSetAttribute(attn_kernel,  cudaFuncAttributeMaxDynamicSharedMemorySize, ATT_SMEM);

    dim3 g1(QKV_OUT/128, (GB*GS)/128);
    gemm_mma_qkv<<<g1, 256, GEMM_SMEM>>>(x, Wqkv);

    rope_kernel<<<GB*GS, 256>>>();

    dim3 ga(GS/64, GH, GB);
    attn_kernel<<<ga, 256, ATT_SMEM>>>();

    dim3 g2(GD/128, (GB*GS)/128);
    gemm_mma_out<<<g2, 256, GEMM_SMEM>>>(Wo, out);
}

// round 5
// speedup vs baseline: 1.5674x; 1.0000x over previous
#include <cuda_runtime.h>
#include <cuda_bf16.h>
#include <math.h>
#include <stdint.h>

// ---------------- problem constants ----------------
#define GB   2
#define GS   2048
#define GD   4096
#define GH   32
#define GKH  8
#define GHD  128
#define QKV_OUT 6144

// ---------------- device scratch ----------------
__device__ float g_qkv[GB*GS*QKV_OUT];
__device__ float g_attn[GB*GS*GD];

// ---------------- f32x2 helpers ----------------
__device__ __forceinline__ unsigned long long pk2(float lo, float hi){
    unsigned long long r;
    asm("mov.b64 %0, {%1, %2};" : "=l"(r) : "f"(lo), "f"(hi));
    return r;
}
__device__ __forceinline__ void fma2(unsigned long long& d, unsigned long long a, unsigned long long b){
    asm("fma.rn.f32x2 %0, %1, %2, %0;" : "+l"(d) : "l"(a), "l"(b));
}
__device__ __forceinline__ void mul2(unsigned long long& d, unsigned long long a){
    asm("mul.rn.f32x2 %0, %1, %2;" : "=l"(d) : "l"(d), "l"(a));
}
__device__ __forceinline__ float2 up2(unsigned long long v){
    float2 f;
    asm("mov.b64 {%0, %1}, %2;" : "=f"(f.x), "=f"(f.y) : "l"(v));
    return f;
}

// ---------------- smem addr helper ----------------
__device__ __forceinline__ uint32_t smem_u32(const void* p){
    uint32_t a;
    asm("{ .reg .u64 t; cvta.to.shared.u64 t, %1; cvt.u32.u64 %0, t; }" : "=r"(a) : "l"(p));
    return a;
}

// ---------------- HMMA helpers (sm_80+ mma.sync, legal on bare sm_103 target) ----------------
__device__ __forceinline__ void ldmx4(uint32_t* r, uint32_t addr){
    asm volatile("ldmatrix.sync.aligned.m8n8.x4.shared.b16 {%0,%1,%2,%3}, [%4];"
        : "=r"(r[0]), "=r"(r[1]), "=r"(r[2]), "=r"(r[3]) : "r"(addr));
}
__device__ __forceinline__ void mma16816(float* c, const uint32_t* a, const uint32_t* b){
    asm volatile(
        "mma.sync.aligned.m16n8k16.row.col.f32.bf16.bf16.f32 "
        "{%0,%1,%2,%3}, {%4,%5,%6,%7}, {%8,%9}, {%0,%1,%2,%3};"
        : "+f"(c[0]), "+f"(c[1]), "+f"(c[2]), "+f"(c[3])
        : "r"(a[0]), "r"(a[1]), "r"(a[2]), "r"(a[3]), "r"(b[0]), "r"(b[1]));
}

// ---------------- hi/lo bf16 split of a float4 ----------------
__device__ __forceinline__ void hilo4(float4 v, unsigned long long& h, unsigned long long& l){
    __nv_bfloat16 h0 = __float2bfloat16(v.x);
    __nv_bfloat16 h1 = __float2bfloat16(v.y);
    __nv_bfloat16 h2 = __float2bfloat16(v.z);
    __nv_bfloat16 h3 = __float2bfloat16(v.w);
    __nv_bfloat16 l0 = __float2bfloat16(v.x - __bfloat162float(h0));
    __nv_bfloat16 l1 = __float2bfloat16(v.y - __bfloat162float(h1));
    __nv_bfloat16 l2 = __float2bfloat16(v.z - __bfloat162float(h2));
    __nv_bfloat16 l3 = __float2bfloat16(v.w - __bfloat162float(h3));
    h = (unsigned long long)__bfloat16_as_ushort(h0)
      | ((unsigned long long)__bfloat16_as_ushort(h1) << 16)
      | ((unsigned long long)__bfloat16_as_ushort(h2) << 32)
      | ((unsigned long long)__bfloat16_as_ushort(h3) << 48);
    l = (unsigned long long)__bfloat16_as_ushort(l0)
      | ((unsigned long long)__bfloat16_as_ushort(l1) << 16)
      | ((unsigned long long)__bfloat16_as_ushort(l2) << 32)
      | ((unsigned long long)__bfloat16_as_ushort(l3) << 48);
}

// ---------------- HMMA bf16x3 GEMM: C[M,N] = A[M,K] * B[N,K]^T ----------------
// CTA tile 128x128, BK=32 (bf16), 256 threads = 8 warps, warp tile 64x32.
// SMEM: 4 tiles (Ah,Al,Bh,Bl), pitch 40 bf16 (80B, conflict-free for ldmatrix),
// double buffered: 4 * 10240 * 2 = 81920 bytes dynamic.
#define GP   80            // row pitch bytes
#define TB   10240         // one tile bytes (128*80)
#define STG  (4*TB)        // one stage
#define GEMM_SMEM (2*STG)

__device__ __forceinline__ void gemm_mma_body(
    const float* __restrict__ A, const float* __restrict__ B, float* __restrict__ C,
    int N, int K)
{
    extern __shared__ __align__(16) char dyn[];
    const uint32_t sb = smem_u32(dyn);

    const int tid  = threadIdx.x;
    const int wid  = tid >> 5;
    const int lane = tid & 31;
    const int wm   = (wid & 1) * 64;    // warp m offset
    const int wn   = (wid >> 1) * 32;   // warp n offset
    const int m0   = blockIdx.y * 128;
    const int n0   = blockIdx.x * 128;

    float acc[4][4][4];
    #pragma unroll
    for (int i=0;i<4;i++)
        #pragma unroll
        for (int j=0;j<4;j++)
            #pragma unroll
            for (int c=0;c<4;c++) acc[i][j][c] = 0.f;

    // loader mapping: 1024 float4 per matrix per stage, 4 per thread
    const int lrow0 = tid >> 3;            // base row for p-loop: row = lrow0 + p*32? no:
    // idx = p*256 + tid; row = idx>>3; c4 = (idx&7)*4
    float4 ra[4], rb[4];

    auto loadG = [&](int k0){
        #pragma unroll
        for (int p=0;p<4;p++){
            const int idx = p*256 + tid;
            const int row = idx >> 3;
            const int c4  = (idx & 7) << 2;
            ra[p] = *(const float4*)(A + (size_t)(m0+row)*K + k0 + c4);
            rb[p] = *(const float4*)(B + (size_t)(n0+row)*K + k0 + c4);
        }
    };
    auto storeS = [&](int s){
        char* base = dyn + s*STG;
        #pragma unroll
        for (int p=0;p<4;p++){
            const int idx = p*256 + tid;
            const int row = idx >> 3;
            const int c4  = (idx & 7) << 2;
            const int off = row*GP + c4*2;
            unsigned long long h, l;
            hilo4(ra[p], h, l);
            *(unsigned long long*)(base + off)       = h;
            *(unsigned long long*)(base + TB + off)  = l;
            hilo4(rb[p], h, l);
            *(unsigned long long*)(base + 2*TB + off) = h;
            *(unsigned long long*)(base + 3*TB + off) = l;
        }
    };

    const int NIT = K / 32;
    loadG(0);
    storeS(0);
    __syncthreads();

    // precomputed lane pieces for ldmatrix addressing
    const int arow = wm + (lane & 15);             // + mi*16
    const int akb  = (lane >> 4) * 16;             // + ks*32
    const int brow = wn + (lane & 7) + ((lane >> 4) << 3);   // + n2*16
    const int bkb  = ((lane >> 3) & 1) * 16;       // + ks*32

    for (int it = 0; it < NIT; ++it){
        if (it + 1 < NIT) loadG((it+1)*32);

        const uint32_t stage = sb + (uint32_t)((it & 1) * STG);
        #pragma unroll
        for (int ks = 0; ks < 2; ++ks){
            uint32_t ah[4][4], al[4][4], bh[2][4], bl[2][4];
            #pragma unroll
            for (int mi = 0; mi < 4; ++mi){
                const uint32_t ad = stage + (uint32_t)((arow + mi*16)*GP + ks*32 + akb);
                ldmx4(ah[mi], ad);
                ldmx4(al[mi], ad + TB);
            }
            #pragma unroll
            for (int n2 = 0; n2 < 2; ++n2){
                const uint32_t bd = stage + (uint32_t)(2*TB + (brow + n2*16)*GP + ks*32 + bkb);
                ldmx4(bh[n2], bd);
                ldmx4(bl[n2], bd + TB);
            }
            #pragma unroll
            for (int mi = 0; mi < 4; ++mi)
                #pragma unroll
                for (int ni = 0; ni < 4; ++ni){
                    const uint32_t* bhp = &bh[ni>>1][(ni&1)*2];
                    const uint32_t* blp = &bl[ni>>1][(ni&1)*2];
                    mma16816(acc[mi][ni], ah[mi], bhp);
                    mma16816(acc[mi][ni], ah[mi], blp);
                    mma16816(acc[mi][ni], al[mi], bhp);
                }
        }
        __syncthreads();
        if (it + 1 < NIT){
            storeS((it+1) & 1);
            __syncthreads();
        }
    }

    // epilogue: direct fp32 stores (float2 per fragment half)
    const int erow = (lane >> 2);
    const int ecol = (lane & 3) * 2;
    #pragma unroll
    for (int mi = 0; mi < 4; ++mi){
        #pragma unroll
        for (int ni = 0; ni < 4; ++ni){
            const int gm = m0 + wm + mi*16 + erow;
            const int gn = n0 + wn + ni*8 + ecol;
            *(float2*)(C + (size_t)gm*N + gn)     = make_float2(acc[mi][ni][0], acc[mi][ni][1]);
            *(float2*)(C + (size_t)(gm+8)*N + gn) = make_float2(acc[mi][ni][2], acc[mi][ni][3]);
        }
    }
}

__global__ __launch_bounds__(256, 1) void gemm_mma_qkv(const float* __restrict__ x,
                                                       const float* __restrict__ Wqkv){
    gemm_mma_body(x, Wqkv, g_qkv, QKV_OUT, GD);
}
__global__ __launch_bounds__(256, 1) void gemm_mma_out(const float* __restrict__ Wo,
                                                       float* __restrict__ out){
    gemm_mma_body(g_attn, Wo, out, GD, GD);
}

// ---------------- RoPE ----------------
__global__ void rope_kernel(){
    const int row = blockIdx.x;
    const float fpos = (float)(row & (GS-1));
    float* base = g_qkv + (size_t)row * QKV_OUT;
    for (int it = threadIdx.x; it < 40*64; it += blockDim.x){
        const int hh = it >> 6;
        const int i  = it & 63;
        float* p = base + (hh < GH ? hh*GHD : GH*GHD + (hh-GH)*GHD);
        const float inv = powf(500000.0f, -(float)i * (1.0f/64.0f));
        const float fr  = fpos * inv;
        float sn, cs;
        sincosf(fr, &sn, &cs);
        const float x1 = p[i], x2 = p[i+64];
        p[i]    = x1*cs - x2*sn;
        p[i+64] = x2*cs + x1*sn;
    }
}

// ---------------- flash attention (fp32 + f32x2, causal, GQA 4:1) ----------------
#define QSTR 68
#define ATT_SMEM ((2*128*QSTR + 64*128 + 64*64)*4)

__global__ __launch_bounds__(256) void attn_kernel(){
    extern __shared__ __align__(16) float sm[];
    float* Qt = sm;                    // [128][QSTR]
    float* Kt = sm + 128*QSTR;         // [128][QSTR]
    float* Vs = sm + 2*128*QSTR;       // [64][128]
    float* Ps = Vs + 64*128;           // [64][64]

    const int tid = threadIdx.x;
    const int ty  = tid >> 4;
    const int tx  = tid & 15;
    const int qt  = blockIdx.x;
    const int h   = blockIdx.y;
    const int b   = blockIdx.z;
    const int kh  = h >> 2;

    const float* qbase = g_qkv + (size_t)b*GS*QKV_OUT + h*GHD;
    const float* kbase = g_qkv + (size_t)b*GS*QKV_OUT + GH*GHD + kh*GHD;
    const float* vbase = kbase + GKH*GHD;

    for (int idx = tid; idx < 64*128; idx += 256){
        const int r = idx >> 7, d = idx & 127;
        Qt[d*QSTR + r] = qbase[(size_t)(qt*64 + r)*QKV_OUT + d];
    }

    float m[4], l[4];
    unsigned long long o2[4][4];
    #pragma unroll
    for (int i = 0; i < 4; ++i){
        m[i] = -1e30f; l[i] = 0.f;
        #pragma unroll
        for (int c = 0; c < 4; ++c) o2[i][c] = 0ULL;
    }
    const float scale = 0.08838834764831845f;

    for (int kt = 0; kt <= qt; ++kt){
        __syncthreads();
        for (int idx = tid; idx < 64*128; idx += 256){
            const int r = idx >> 7, d = idx & 127;
            const size_t grow = (size_t)(kt*64 + r)*QKV_OUT + d;
            Kt[d*QSTR + r] = kbase[grow];
            Vs[idx]        = vbase[grow];
        }
        __syncthreads();

        unsigned long long s2[4][2];
        #pragma unroll
        for (int i = 0; i < 4; ++i){ s2[i][0] = 0ULL; s2[i][1] = 0ULL; }

        #pragma unroll 4
        for (int d = 0; d < 128; ++d){
            const float4 q4 = *(const float4*)&Qt[d*QSTR + ty*4];
            const float4 k4 = *(const float4*)&Kt[d*QSTR + tx*4];
            const unsigned long long kp0 = pk2(k4.x, k4.y);
            const unsigned long long kp1 = pk2(k4.z, k4.w);
            const float qv[4] = {q4.x, q4.y, q4.z, q4.w};
            #pragma unroll
            for (int i = 0; i < 4; ++i){
                const unsigned long long ap = pk2(qv[i], qv[i]);
                fma2(s2[i][0], ap, kp0);
                fma2(s2[i][1], ap, kp1);
            }
        }

        const bool diag = (kt == qt);
        #pragma unroll
        for (int i = 0; i < 4; ++i){
            const int qrow = qt*64 + ty*4 + i;
            const float2 pa = up2(s2[i][0]);
            const float2 pb = up2(s2[i][1]);
            float sv[4] = {pa.x, pa.y, pb.x, pb.y};
            float rm = -1e30f;
            #pragma unroll
            for (int j = 0; j < 4; ++j){
                float v = sv[j]*scale;
                if (diag && (kt*64 + tx*4 + j) > qrow) v = -1e30f;
                sv[j] = v; rm = fmaxf(rm, v);
            }
            #pragma unroll
            for (int off = 8; off > 0; off >>= 1)
                rm = fmaxf(rm, __shfl_xor_sync(0xffffffffu, rm, off));
            const float mn    = fmaxf(m[i], rm);
            const float alpha = expf(m[i] - mn);
            float ps = 0.f;
            #pragma unroll
            for (int j = 0; j < 4; ++j){
                const float p = expf(sv[j] - mn);
                ps += p;
                Ps[(ty*4+i)*64 + tx*4 + j] = p;
            }
            #pragma unroll
            for (int off = 8; off > 0; off >>= 1)
                ps += __shfl_xor_sync(0xffffffffu, ps, off);
            l[i] = l[i]*alpha + ps;
            m[i] = mn;
            const unsigned long long am = pk2(alpha, alpha);
            #pragma unroll
            for (int c = 0; c < 4; ++c) mul2(o2[i][c], am);
        }
        __syncthreads();

        #pragma unroll 2
        for (int kk = 0; kk < 64; ++kk){
            const float4 v0 = *(const float4*)&Vs[kk*128 + tx*8];
            const float4 v1 = *(const float4*)&Vs[kk*128 + tx*8 + 4];
            const unsigned long long vp[4] = {
                pk2(v0.x, v0.y), pk2(v0.z, v0.w), pk2(v1.x, v1.y), pk2(v1.z, v1.w)
            };
            #pragma unroll
            for (int i = 0; i < 4; ++i){
                const float p = Ps[(ty*4+i)*64 + kk];
                const unsigned long long pp = pk2(p, p);
                #pragma unroll
                for (int c = 0; c < 4; ++c) fma2(o2[i][c], pp, vp[c]);
            }
        }
    }

    #pragma unroll
    for (int i = 0; i < 4; ++i){
        const int qrow = qt*64 + ty*4 + i;
        const float inv = 1.0f / l[i];
        float* op = g_attn + ((size_t)(b*GS + qrow))*GD + h*GHD + tx*8;
        const float2 a0 = up2(o2[i][0]), a1 = up2(o2[i][1]);
        const float2 a2 = up2(o2[i][2]), a3 = up2(o2[i][3]);
        *(float4*)op     = make_float4(a0.x*inv, a0.y*inv, a1.x*inv, a1.y*inv);
        *(float4*)(op+4) = make_float4(a2.x*inv, a2.y*inv, a3.x*inv, a3.y*inv);
    }
}

// ---------------- launch ----------------
extern "C" void kernel_launch(void* const* d_in, const int* in_sizes, int n_in,
                              void* d_out, int out_size)
{
    const float* x    = (const float*)d_in[0];
    const float* Wqkv = (const float*)d_in[1];
    const float* Wo   = (const float*)d_in[2];
    float* out = (float*)d_out;

    cudaFuncSetAttribute(gemm_mma_qkv, cudaFuncAttributeMaxDynamicSharedMemorySize, GEMM_SMEM);
    cudaFuncSetAttribute(gemm_mma_out, cudaFuncAttributeMaxDynamicSharedMemorySize, GEMM_SMEM);
    cudaFuncSetAttribute(attn_kernel,  cudaFuncAttributeMaxDynamicSharedMemorySize, ATT_SMEM);

    dim3 g1(QKV_OUT/128, (GB*GS)/128);
    gemm_mma_qkv<<<g1, 256, GEMM_SMEM>>>(x, Wqkv);

    rope_kernel<<<GB*GS, 256>>>();

    dim3 ga(GS/64, GH, GB);
    attn_kernel<<<ga, 256, ATT_SMEM>>>();

    dim3 g2(GD/128, (GB*GS)/128);
    gemm_mma_out<<<g2, 256, GEMM_SMEM>>>(Wo, out);
}

// round 6
// speedup vs baseline: 1.6908x; 1.0788x over previous
#include <cuda_runtime.h>
#include <cuda_bf16.h>
#include <math.h>
#include <stdint.h>

// ---------------- problem constants ----------------
#define GB   2
#define GS   2048
#define GD   4096
#define GH   32
#define GKH  8
#define GHD  128
#define QKV_OUT 6144

// ---------------- device scratch ----------------
__device__ float g_qkv[GB*GS*QKV_OUT];                 // fp32 qkv (rope + attention input)
__device__ __nv_bfloat16 g_xh[GB*GS*GD],   g_xl[GB*GS*GD];
__device__ __nv_bfloat16 g_wqkvh[QKV_OUT*GD], g_wqkvl[QKV_OUT*GD];
__device__ __nv_bfloat16 g_woh[GD*GD],     g_wol[GD*GD];
__device__ __nv_bfloat16 g_attnh[GB*GS*GD], g_attnl[GB*GS*GD];

// ---------------- f32x2 helpers ----------------
__device__ __forceinline__ unsigned long long pk2(float lo, float hi){
    unsigned long long r;
    asm("mov.b64 %0, {%1, %2};" : "=l"(r) : "f"(lo), "f"(hi));
    return r;
}
__device__ __forceinline__ void fma2(unsigned long long& d, unsigned long long a, unsigned long long b){
    asm("fma.rn.f32x2 %0, %1, %2, %0;" : "+l"(d) : "l"(a), "l"(b));
}
__device__ __forceinline__ void mul2(unsigned long long& d, unsigned long long a){
    asm("mul.rn.f32x2 %0, %1, %2;" : "=l"(d) : "l"(d), "l"(a));
}
__device__ __forceinline__ float2 up2(unsigned long long v){
    float2 f;
    asm("mov.b64 {%0, %1}, %2;" : "=f"(f.x), "=f"(f.y) : "l"(v));
    return f;
}

// ---------------- smem addr helper ----------------
__device__ __forceinline__ uint32_t smem_u32(const void* p){
    uint32_t a;
    asm("{ .reg .u64 t; cvta.to.shared.u64 t, %1; cvt.u32.u64 %0, t; }" : "=r"(a) : "l"(p));
    return a;
}

// ---------------- HMMA / cp.async helpers ----------------
__device__ __forceinline__ void ldmx4(uint32_t* r, uint32_t addr){
    asm volatile("ldmatrix.sync.aligned.m8n8.x4.shared.b16 {%0,%1,%2,%3}, [%4];"
        : "=r"(r[0]), "=r"(r[1]), "=r"(r[2]), "=r"(r[3]) : "r"(addr));
}
__device__ __forceinline__ void mma16816(float* c, const uint32_t* a, const uint32_t* b){
    asm volatile(
        "mma.sync.aligned.m16n8k16.row.col.f32.bf16.bf16.f32 "
        "{%0,%1,%2,%3}, {%4,%5,%6,%7}, {%8,%9}, {%0,%1,%2,%3};"
        : "+f"(c[0]), "+f"(c[1]), "+f"(c[2]), "+f"(c[3])
        : "r"(a[0]), "r"(a[1]), "r"(a[2]), "r"(a[3]), "r"(b[0]), "r"(b[1]));
}
__device__ __forceinline__ void cp16(uint32_t saddr, const void* g){
    asm volatile("cp.async.cg.shared.global [%0], [%1], 16;"
        :: "r"(saddr), "l"(__cvta_generic_to_global(g)) : "memory");
}
__device__ __forceinline__ void cp_commit(){
    asm volatile("cp.async.commit_group;" ::: "memory");
}
template <int N>
__device__ __forceinline__ void cp_wait(){
    asm volatile("cp.async.wait_group %0;" :: "n"(N) : "memory");
}

// ---------------- hi/lo bf16 split of a float4 ----------------
__device__ __forceinline__ void hilo4(float4 v, unsigned long long& h, unsigned long long& l){
    __nv_bfloat16 h0 = __float2bfloat16(v.x);
    __nv_bfloat16 h1 = __float2bfloat16(v.y);
    __nv_bfloat16 h2 = __float2bfloat16(v.z);
    __nv_bfloat16 h3 = __float2bfloat16(v.w);
    __nv_bfloat16 l0 = __float2bfloat16(v.x - __bfloat162float(h0));
    __nv_bfloat16 l1 = __float2bfloat16(v.y - __bfloat162float(h1));
    __nv_bfloat16 l2 = __float2bfloat16(v.z - __bfloat162float(h2));
    __nv_bfloat16 l3 = __float2bfloat16(v.w - __bfloat162float(h3));
    h = (unsigned long long)__bfloat16_as_ushort(h0)
      | ((unsigned long long)__bfloat16_as_ushort(h1) << 16)
      | ((unsigned long long)__bfloat16_as_ushort(h2) << 32)
      | ((unsigned long long)__bfloat16_as_ushort(h3) << 48);
    l = (unsigned long long)__bfloat16_as_ushort(l0)
      | ((unsigned long long)__bfloat16_as_ushort(l1) << 16)
      | ((unsigned long long)__bfloat16_as_ushort(l2) << 32)
      | ((unsigned long long)__bfloat16_as_ushort(l3) << 48);
}

// ---------------- fp32 -> bf16 hi/lo conversion kernel ----------------
__global__ __launch_bounds__(256) void cvt_pair_kernel(const float4* __restrict__ src,
                                                       unsigned long long* __restrict__ h,
                                                       unsigned long long* __restrict__ l,
                                                       int n4){
    const int i = blockIdx.x*blockDim.x + threadIdx.x;
    if (i < n4){
        unsigned long long hh, ll;
        hilo4(src[i], hh, ll);
        h[i] = hh;
        l[i] = ll;
    }
}

// ---------------- HMMA bf16x3 GEMM with cp.async 3-stage pipeline ----------------
// C[M,N] = A[M,K]*B[N,K]^T where A ~ Ah+Al, B ~ Bh+Bl (bf16 inputs, precomputed).
// CTA tile 128x128, BK=32, 8 warps (warp tile 64x32), smem pitch 80B, 3 stages.
#define GP   80
#define TB   10240          // 128*80
#define STG  (4*TB)         // Ah,Al,Bh,Bl
#define NSTAGE 3
#define GEMM_SMEM (NSTAGE*STG)   // 122880 B

__device__ __forceinline__ void gemm_bf16x3_body(
    const __nv_bfloat16* __restrict__ Ah, const __nv_bfloat16* __restrict__ Al,
    const __nv_bfloat16* __restrict__ Bh, const __nv_bfloat16* __restrict__ Bl,
    float* __restrict__ C, int N, int K)
{
    extern __shared__ __align__(16) char dyn[];
    const uint32_t sb = smem_u32(dyn);

    const int tid  = threadIdx.x;
    const int wid  = tid >> 5;
    const int lane = tid & 31;
    const int wm   = (wid & 1) * 64;
    const int wn   = (wid >> 1) * 32;
    const int m0   = blockIdx.y * 128;
    const int n0   = blockIdx.x * 128;

    const __nv_bfloat16* gbase[4] = {
        Ah + (size_t)m0*K, Al + (size_t)m0*K,
        Bh + (size_t)n0*K, Bl + (size_t)n0*K
    };
    const int r0  = tid >> 2;        // 0..63
    const int c16 = tid & 3;         // 16B chunk in 64B row

    auto issue = [&](int s, int k0){
        const uint32_t stg = sb + (uint32_t)(s*STG);
        #pragma unroll
        for (int p = 0; p < 8; ++p){
            const int t   = p >> 1;
            const int row = (p & 1)*64 + r0;
            const uint32_t sa = stg + (uint32_t)(t*TB + row*GP + c16*16);
            cp16(sa, gbase[t] + (size_t)row*K + k0 + c16*8);
        }
        cp_commit();
    };

    float acc[4][4][4];
    #pragma unroll
    for (int i=0;i<4;i++)
        #pragma unroll
        for (int j=0;j<4;j++)
            #pragma unroll
            for (int c=0;c<4;c++) acc[i][j][c] = 0.f;

    const int NIT = K / 32;
    issue(0, 0);
    issue(1, 32);

    // ldmatrix lane addressing (same layout as validated R5 kernel)
    const int arow = wm + (lane & 15);
    const int akb  = (lane >> 4) * 16;
    const int brow = wn + (lane & 7) + ((lane >> 4) << 3);
    const int bkb  = ((lane >> 3) & 1) * 16;

    for (int it = 0; it < NIT; ++it){
        if (it < NIT-1) cp_wait<1>(); else cp_wait<0>();
        __syncthreads();
        if (it + 2 < NIT) issue((it+2) % NSTAGE, (it+2)*32);

        const uint32_t stage = sb + (uint32_t)((it % NSTAGE) * STG);
        #pragma unroll
        for (int ks = 0; ks < 2; ++ks){
            uint32_t ah[4][4], al[4][4], bh[2][4], bl[2][4];
            #pragma unroll
            for (int mi = 0; mi < 4; ++mi){
                const uint32_t ad = stage + (uint32_t)((arow + mi*16)*GP + ks*32 + akb);
                ldmx4(ah[mi], ad);
                ldmx4(al[mi], ad + TB);
            }
            #pragma unroll
            for (int n2 = 0; n2 < 2; ++n2){
                const uint32_t bd = stage + (uint32_t)(2*TB + (brow + n2*16)*GP + ks*32 + bkb);
                ldmx4(bh[n2], bd);
                ldmx4(bl[n2], bd + TB);
            }
            #pragma unroll
            for (int mi = 0; mi < 4; ++mi)
                #pragma unroll
                for (int ni = 0; ni < 4; ++ni){
                    const uint32_t* bhp = &bh[ni>>1][(ni&1)*2];
                    const uint32_t* blp = &bl[ni>>1][(ni&1)*2];
                    mma16816(acc[mi][ni], ah[mi], bhp);
                    mma16816(acc[mi][ni], ah[mi], blp);
                    mma16816(acc[mi][ni], al[mi], bhp);
                }
        }
        __syncthreads();
    }

    const int erow = (lane >> 2);
    const int ecol = (lane & 3) * 2;
    #pragma unroll
    for (int mi = 0; mi < 4; ++mi){
        #pragma unroll
        for (int ni = 0; ni < 4; ++ni){
            const int gm = m0 + wm + mi*16 + erow;
            const int gn = n0 + wn + ni*8 + ecol;
            *(float2*)(C + (size_t)gm*N + gn)     = make_float2(acc[mi][ni][0], acc[mi][ni][1]);
            *(float2*)(C + (size_t)(gm+8)*N + gn) = make_float2(acc[mi][ni][2], acc[mi][ni][3]);
        }
    }
}

__global__ __launch_bounds__(256, 1) void gemm_qkv_kernel(){
    gemm_bf16x3_body(g_xh, g_xl, g_wqkvh, g_wqkvl, g_qkv, QKV_OUT, GD);
}
__global__ __launch_bounds__(256, 1) void gemm_out_kernel(float* __restrict__ out){
    gemm_bf16x3_body(g_attnh, g_attnl, g_woh, g_wol, out, GD, GD);
}

// ---------------- RoPE ----------------
__global__ void rope_kernel(){
    const int row = blockIdx.x;
    const float fpos = (float)(row & (GS-1));
    float* base = g_qkv + (size_t)row * QKV_OUT;
    for (int it = threadIdx.x; it < 40*64; it += blockDim.x){
        const int hh = it >> 6;
        const int i  = it & 63;
        float* p = base + (hh < GH ? hh*GHD : GH*GHD + (hh-GH)*GHD);
        const float inv = powf(500000.0f, -(float)i * (1.0f/64.0f));
        const float fr  = fpos * inv;
        float sn, cs;
        sincosf(fr, &sn, &cs);
        const float x1 = p[i], x2 = p[i+64];
        p[i]    = x1*cs - x2*sn;
        p[i+64] = x2*cs + x1*sn;
    }
}

// ---------------- flash attention (fp32 + f32x2, causal, GQA 4:1) ----------------
#define QSTR 68
#define ATT_SMEM ((2*128*QSTR + 64*128 + 64*64)*4)

__global__ __launch_bounds__(256) void attn_kernel(){
    extern __shared__ __align__(16) float sm[];
    float* Qt = sm;                    // [128][QSTR]
    float* Kt = sm + 128*QSTR;         // [128][QSTR]
    float* Vs = sm + 2*128*QSTR;       // [64][128]
    float* Ps = Vs + 64*128;           // [64][64]

    const int tid = threadIdx.x;
    const int ty  = tid >> 4;
    const int tx  = tid & 15;
    const int qt  = blockIdx.x;
    const int h   = blockIdx.y;
    const int b   = blockIdx.z;
    const int kh  = h >> 2;

    const float* qbase = g_qkv + (size_t)b*GS*QKV_OUT + h*GHD;
    const float* kbase = g_qkv + (size_t)b*GS*QKV_OUT + GH*GHD + kh*GHD;
    const float* vbase = kbase + GKH*GHD;

    for (int idx = tid; idx < 64*128; idx += 256){
        const int r = idx >> 7, d = idx & 127;
        Qt[d*QSTR + r] = qbase[(size_t)(qt*64 + r)*QKV_OUT + d];
    }

    float m[4], l[4];
    unsigned long long o2[4][4];
    #pragma unroll
    for (int i = 0; i < 4; ++i){
        m[i] = -1e30f; l[i] = 0.f;
        #pragma unroll
        for (int c = 0; c < 4; ++c) o2[i][c] = 0ULL;
    }
    const float scale = 0.08838834764831845f;

    for (int kt = 0; kt <= qt; ++kt){
        __syncthreads();
        for (int idx = tid; idx < 64*128; idx += 256){
            const int r = idx >> 7, d = idx & 127;
            const size_t grow = (size_t)(kt*64 + r)*QKV_OUT + d;
            Kt[d*QSTR + r] = kbase[grow];
            Vs[idx]        = vbase[grow];
        }
        __syncthreads();

        unsigned long long s2[4][2];
        #pragma unroll
        for (int i = 0; i < 4; ++i){ s2[i][0] = 0ULL; s2[i][1] = 0ULL; }

        #pragma unroll 4
        for (int d = 0; d < 128; ++d){
            const float4 q4 = *(const float4*)&Qt[d*QSTR + ty*4];
            const float4 k4 = *(const float4*)&Kt[d*QSTR + tx*4];
            const unsigned long long kp0 = pk2(k4.x, k4.y);
            const unsigned long long kp1 = pk2(k4.z, k4.w);
            const float qv[4] = {q4.x, q4.y, q4.z, q4.w};
            #pragma unroll
            for (int i = 0; i < 4; ++i){
                const unsigned long long ap = pk2(qv[i], qv[i]);
                fma2(s2[i][0], ap, kp0);
                fma2(s2[i][1], ap, kp1);
            }
        }

        const bool diag = (kt == qt);
        #pragma unroll
        for (int i = 0; i < 4; ++i){
            const int qrow = qt*64 + ty*4 + i;
            const float2 pa = up2(s2[i][0]);
            const float2 pb = up2(s2[i][1]);
            float sv[4] = {pa.x, pa.y, pb.x, pb.y};
            float rm = -1e30f;
            #pragma unroll
            for (int j = 0; j < 4; ++j){
                float v = sv[j]*scale;
                if (diag && (kt*64 + tx*4 + j) > qrow) v = -1e30f;
                sv[j] = v; rm = fmaxf(rm, v);
            }
            #pragma unroll
            for (int off = 8; off > 0; off >>= 1)
                rm = fmaxf(rm, __shfl_xor_sync(0xffffffffu, rm, off));
            const float mn    = fmaxf(m[i], rm);
            const float alpha = expf(m[i] - mn);
            float ps = 0.f;
            #pragma unroll
            for (int j = 0; j < 4; ++j){
                const float p = expf(sv[j] - mn);
                ps += p;
                Ps[(ty*4+i)*64 + tx*4 + j] = p;
            }
            #pragma unroll
            for (int off = 8; off > 0; off >>= 1)
                ps += __shfl_xor_sync(0xffffffffu, ps, off);
            l[i] = l[i]*alpha + ps;
            m[i] = mn;
            const unsigned long long am = pk2(alpha, alpha);
            #pragma unroll
            for (int c = 0; c < 4; ++c) mul2(o2[i][c], am);
        }
        __syncthreads();

        #pragma unroll 2
        for (int kk = 0; kk < 64; ++kk){
            const float4 v0 = *(const float4*)&Vs[kk*128 + tx*8];
            const float4 v1 = *(const float4*)&Vs[kk*128 + tx*8 + 4];
            const unsigned long long vp[4] = {
                pk2(v0.x, v0.y), pk2(v0.z, v0.w), pk2(v1.x, v1.y), pk2(v1.z, v1.w)
            };
            #pragma unroll
            for (int i = 0; i < 4; ++i){
                const float p = Ps[(ty*4+i)*64 + kk];
                const unsigned long long pp = pk2(p, p);
                #pragma unroll
                for (int c = 0; c < 4; ++c) fma2(o2[i][c], pp, vp[c]);
            }
        }
    }

    // epilogue: O /= l, write bf16 hi/lo directly (out-proj GEMM operand)
    #pragma unroll
    for (int i = 0; i < 4; ++i){
        const int qrow = qt*64 + ty*4 + i;
        const float inv = 1.0f / l[i];
        const float2 a0 = up2(o2[i][0]), a1 = up2(o2[i][1]);
        const float2 a2 = up2(o2[i][2]), a3 = up2(o2[i][3]);
        const float4 v0 = make_float4(a0.x*inv, a0.y*inv, a1.x*inv, a1.y*inv);
        const float4 v1 = make_float4(a2.x*inv, a2.y*inv, a3.x*inv, a3.y*inv);
        unsigned long long h0, l0, h1, l1;
        hilo4(v0, h0, l0);
        hilo4(v1, h1, l1);
        const size_t off = ((size_t)(b*GS + qrow))*GD + h*GHD + tx*8;
        *(unsigned long long*)(g_attnh + off)     = h0;
        *(unsigned long long*)(g_attnh + off + 4) = h1;
        *(unsigned long long*)(g_attnl + off)     = l0;
        *(unsigned long long*)(g_attnl + off + 4) = l1;
    }
}

// ---------------- launch ----------------
extern "C" void kernel_launch(void* const* d_in, const int* in_sizes, int n_in,
                              void* d_out, int out_size)
{
    const float* x    = (const float*)d_in[0];
    const float* Wqkv = (const float*)d_in[1];
    const float* Wo   = (const float*)d_in[2];
    float* out = (float*)d_out;

    cudaFuncSetAttribute(gemm_qkv_kernel, cudaFuncAttributeMaxDynamicSharedMemorySize, GEMM_SMEM);
    cudaFuncSetAttribute(gemm_out_kernel, cudaFuncAttributeMaxDynamicSharedMemorySize, GEMM_SMEM);
    cudaFuncSetAttribute(attn_kernel,     cudaFuncAttributeMaxDynamicSharedMemorySize, ATT_SMEM);

    // resolve device scratch symbols (host-side addresses of __device__ arrays)
    unsigned long long *xh, *xl, *wqh, *wql, *woh, *wol;
    cudaGetSymbolAddress((void**)&xh,  g_xh);
    cudaGetSymbolAddress((void**)&xl,  g_xl);
    cudaGetSymbolAddress((void**)&wqh, g_wqkvh);
    cudaGetSymbolAddress((void**)&wql, g_wqkvl);
    cudaGetSymbolAddress((void**)&woh, g_woh);
    cudaGetSymbolAddress((void**)&wol, g_wol);

    // fp32 -> bf16 hi/lo conversions
    const int nx  = GB*GS*GD/4;      // 4194304 float4
    const int nwq = QKV_OUT*GD/4;    // 6291456
    const int nwo = GD*GD/4;         // 4194304
    cvt_pair_kernel<<<(nx +255)/256, 256>>>((const float4*)x,    xh,  xl,  nx);
    cvt_pair_kernel<<<(nwq+255)/256, 256>>>((const float4*)Wqkv, wqh, wql, nwq);
    cvt_pair_kernel<<<(nwo+255)/256, 256>>>((const float4*)Wo,   woh, wol, nwo);

    dim3 g1(QKV_OUT/128, (GB*GS)/128);
    gemm_qkv_kernel<<<g1, 256, GEMM_SMEM>>>();

    rope_kernel<<<GB*GS, 256>>>();

    dim3 ga(GS/64, GH, GB);
    attn_kernel<<<ga, 256, ATT_SMEM>>>();

    dim3 g2(GD/128, (GB*GS)/128);
    gemm_out_kernel<<<g2, 256, GEMM_SMEM>>>(out);
}

// round 7
// speedup vs baseline: 3.1214x; 1.8461x over previous
#include <cuda_runtime.h>
#include <cuda_bf16.h>
#include <math.h>
#include <stdint.h>

// ---------------- problem constants ----------------
#define GB   2
#define GS   2048
#define GD   4096
#define GH   32
#define GKH  8
#define GHD  128
#define QKV_OUT 6144
#define QKSTRIDE 5120     // q(4096) + k(1024) packed

// ---------------- device scratch ----------------
__device__ float g_qkv[GB*GS*QKV_OUT];                       // fp32 qkv (gemm out, rope)
__device__ __nv_bfloat16 g_xh[GB*GS*GD],      g_xl[GB*GS*GD];
__device__ __nv_bfloat16 g_wqkvh[QKV_OUT*GD], g_wqkvl[QKV_OUT*GD];
__device__ __nv_bfloat16 g_woh[GD*GD],        g_wol[GD*GD];
__device__ __nv_bfloat16 g_attnh[GB*GS*GD],   g_attnl[GB*GS*GD];
__device__ __nv_bfloat16 g_qkh[GB*GS*QKSTRIDE], g_qkl[GB*GS*QKSTRIDE];   // roped q(scaled)+k, bf16 hi/lo
__device__ __nv_bfloat16 g_vth[GB*GKH*GHD*GS],  g_vtl[GB*GKH*GHD*GS];    // V transposed [b,kh,d,s]

// ---------------- smem addr helper ----------------
__device__ __forceinline__ uint32_t smem_u32(const void* p){
    uint32_t a;
    asm("{ .reg .u64 t; cvta.to.shared.u64 t, %1; cvt.u32.u64 %0, t; }" : "=r"(a) : "l"(p));
    return a;
}

// ---------------- HMMA / cp.async helpers ----------------
__device__ __forceinline__ void ldmx4(uint32_t* r, uint32_t addr){
    asm volatile("ldmatrix.sync.aligned.m8n8.x4.shared.b16 {%0,%1,%2,%3}, [%4];"
        : "=r"(r[0]), "=r"(r[1]), "=r"(r[2]), "=r"(r[3]) : "r"(addr));
}
__device__ __forceinline__ void mma16816(float* c, const uint32_t* a, const uint32_t* b){
    asm volatile(
        "mma.sync.aligned.m16n8k16.row.col.f32.bf16.bf16.f32 "
        "{%0,%1,%2,%3}, {%4,%5,%6,%7}, {%8,%9}, {%0,%1,%2,%3};"
        : "+f"(c[0]), "+f"(c[1]), "+f"(c[2]), "+f"(c[3])
        : "r"(a[0]), "r"(a[1]), "r"(a[2]), "r"(a[3]), "r"(b[0]), "r"(b[1]));
}
__device__ __forceinline__ void cp16(uint32_t saddr, const void* g){
    asm volatile("cp.async.cg.shared.global [%0], [%1], 16;"
        :: "r"(saddr), "l"(__cvta_generic_to_global(g)) : "memory");
}
__device__ __forceinline__ void cp_commit(){
    asm volatile("cp.async.commit_group;" ::: "memory");
}
template <int N>
__device__ __forceinline__ void cp_wait(){
    asm volatile("cp.async.wait_group %0;" :: "n"(N) : "memory");
}

// ---------------- bf16 hi/lo helpers ----------------
__device__ __forceinline__ void hilo4(float4 v, unsigned long long& h, unsigned long long& l){
    __nv_bfloat16 h0 = __float2bfloat16(v.x);
    __nv_bfloat16 h1 = __float2bfloat16(v.y);
    __nv_bfloat16 h2 = __float2bfloat16(v.z);
    __nv_bfloat16 h3 = __float2bfloat16(v.w);
    __nv_bfloat16 l0 = __float2bfloat16(v.x - __bfloat162float(h0));
    __nv_bfloat16 l1 = __float2bfloat16(v.y - __bfloat162float(h1));
    __nv_bfloat16 l2 = __float2bfloat16(v.z - __bfloat162float(h2));
    __nv_bfloat16 l3 = __float2bfloat16(v.w - __bfloat162float(h3));
    h = (unsigned long long)__bfloat16_as_ushort(h0)
      | ((unsigned long long)__bfloat16_as_ushort(h1) << 16)
      | ((unsigned long long)__bfloat16_as_ushort(h2) << 32)
      | ((unsigned long long)__bfloat16_as_ushort(h3) << 48);
    l = (unsigned long long)__bfloat16_as_ushort(l0)
      | ((unsigned long long)__bfloat16_as_ushort(l1) << 16)
      | ((unsigned long long)__bfloat16_as_ushort(l2) << 32)
      | ((unsigned long long)__bfloat16_as_ushort(l3) << 48);
}
__device__ __forceinline__ void packhl(float f0, float f1, uint32_t& h, uint32_t& l){
    __nv_bfloat16 h0 = __float2bfloat16(f0);
    __nv_bfloat16 h1 = __float2bfloat16(f1);
    __nv_bfloat16 b0 = __float2bfloat16(f0 - __bfloat162float(h0));
    __nv_bfloat16 b1 = __float2bfloat16(f1 - __bfloat162float(h1));
    h = (uint32_t)__bfloat16_as_ushort(h0) | ((uint32_t)__bfloat16_as_ushort(h1) << 16);
    l = (uint32_t)__bfloat16_as_ushort(b0) | ((uint32_t)__bfloat16_as_ushort(b1) << 16);
}

// ---------------- fp32 -> bf16 hi/lo (same layout) ----------------
__global__ __launch_bounds__(256) void cvt_pair_kernel(const float4* __restrict__ src,
                                                       unsigned long long* __restrict__ h,
                                                       unsigned long long* __restrict__ l,
                                                       int n4){
    const int i = blockIdx.x*blockDim.x + threadIdx.x;
    if (i < n4){
        unsigned long long hh, ll;
        hilo4(src[i], hh, ll);
        h[i] = hh;
        l[i] = ll;
    }
}

// ---------------- q+k region -> bf16 hi/lo (6144 stride -> 5120 stride) ----------------
__global__ __launch_bounds__(256) void qkconv_kernel(){
    const int i = blockIdx.x*blockDim.x + threadIdx.x;   // over B*S*5120/4
    const int n4 = GB*GS*QKSTRIDE/4;
    if (i >= n4) return;
    const int row = i / (QKSTRIDE/4);
    const int c   = i - row*(QKSTRIDE/4);
    const float4 v = *(const float4*)(g_qkv + (size_t)row*QKV_OUT + c*4);
    unsigned long long h, l;
    hilo4(v, h, l);
    *(unsigned long long*)(g_qkh + (size_t)row*QKSTRIDE + c*4) = h;
    *(unsigned long long*)(g_qkl + (size_t)row*QKSTRIDE + c*4) = l;
}

// ---------------- V transpose conversion: [b,s,kh,d] -> [b,kh,d,s] bf16 hi/lo ----------------
__global__ void vconv_kernel(){
    __shared__ float t[32][33];
    const int s0 = blockIdx.x*32;
    const int d0 = blockIdx.y*32;
    const int bkh = blockIdx.z;           // b*8+kh
    const int b  = bkh >> 3, kh = bkh & 7;
    #pragma unroll
    for (int i = 0; i < 4; ++i){
        const int s = s0 + threadIdx.y + i*8;
        const int d = d0 + threadIdx.x;
        t[threadIdx.y + i*8][threadIdx.x] =
            g_qkv[(size_t)(b*GS + s)*QKV_OUT + QKSTRIDE + kh*GHD + d];
    }
    __syncthreads();
    #pragma unroll
    for (int i = 0; i < 4; ++i){
        const int d = d0 + threadIdx.y + i*8;
        const int s = s0 + threadIdx.x;
        const float v = t[threadIdx.x][threadIdx.y + i*8];
        const __nv_bfloat16 h = __float2bfloat16(v);
        const __nv_bfloat16 l = __float2bfloat16(v - __bfloat162float(h));
        const size_t o = ((size_t)(bkh*GHD + d))*GS + s;
        g_vth[o] = h;
        g_vtl[o] = l;
    }
}

// ---------------- HMMA bf16x3 GEMM, 2-stage cp.async, 2 CTAs/SM ----------------
#define GP   80
#define TB   10240          // 128*80
#define STG  (4*TB)         // Ah,Al,Bh,Bl
#define GEMM_SMEM (2*STG)   // 81920

__device__ __forceinline__ void gemm_bf16x3_body(
    const __nv_bfloat16* __restrict__ Ah, const __nv_bfloat16* __restrict__ Al,
    const __nv_bfloat16* __restrict__ Bh, const __nv_bfloat16* __restrict__ Bl,
    float* __restrict__ C, int N, int K)
{
    extern __shared__ __align__(16) char dyn[];
    const uint32_t sb = smem_u32(dyn);

    const int tid  = threadIdx.x;
    const int wid  = tid >> 5;
    const int lane = tid & 31;
    const int wm   = (wid & 1) * 64;
    const int wn   = (wid >> 1) * 32;
    const int m0   = blockIdx.y * 128;
    const int n0   = blockIdx.x * 128;

    const __nv_bfloat16* gbase[4] = {
        Ah + (size_t)m0*K, Al + (size_t)m0*K,
        Bh + (size_t)n0*K, Bl + (size_t)n0*K
    };
    const int r0  = tid >> 2;
    const int c16 = tid & 3;

    auto issue = [&](int s, int k0){
        const uint32_t stg = sb + (uint32_t)(s*STG);
        #pragma unroll
        for (int p = 0; p < 8; ++p){
            const int t   = p >> 1;
            const int row = (p & 1)*64 + r0;
            cp16(stg + (uint32_t)(t*TB + row*GP + c16*16),
                 gbase[t] + (size_t)row*K + k0 + c16*8);
        }
        cp_commit();
    };

    float acc[4][4][4];
    #pragma unroll
    for (int i=0;i<4;i++)
        #pragma unroll
        for (int j=0;j<4;j++)
            #pragma unroll
            for (int c=0;c<4;c++) acc[i][j][c] = 0.f;

    const int NIT = K / 32;
    issue(0, 0);

    const int arow = wm + (lane & 15);
    const int akb  = (lane >> 4) * 16;
    const int brow = wn + (lane & 7) + ((lane >> 4) << 3);
    const int bkb  = ((lane >> 3) & 1) * 16;

    for (int it = 0; it < NIT; ++it){
        cp_wait<0>();
        __syncthreads();
        if (it + 1 < NIT) issue((it+1) & 1, (it+1)*32);

        const uint32_t stage = sb + (uint32_t)((it & 1) * STG);
        #pragma unroll
        for (int ks = 0; ks < 2; ++ks){
            uint32_t ah[4][4], al[4][4], bh[2][4], bl[2][4];
            #pragma unroll
            for (int mi = 0; mi < 4; ++mi){
                const uint32_t ad = stage + (uint32_t)((arow + mi*16)*GP + ks*32 + akb);
                ldmx4(ah[mi], ad);
                ldmx4(al[mi], ad + TB);
            }
            #pragma unroll
            for (int n2 = 0; n2 < 2; ++n2){
                const uint32_t bd = stage + (uint32_t)(2*TB + (brow + n2*16)*GP + ks*32 + bkb);
                ldmx4(bh[n2], bd);
                ldmx4(bl[n2], bd + TB);
            }
            #pragma unroll
            for (int mi = 0; mi < 4; ++mi)
                #pragma unroll
                for (int ni = 0; ni < 4; ++ni){
                    const uint32_t* bhp = &bh[ni>>1][(ni&1)*2];
                    const uint32_t* blp = &bl[ni>>1][(ni&1)*2];
                    mma16816(acc[mi][ni], ah[mi], bhp);
                    mma16816(acc[mi][ni], ah[mi], blp);
                    mma16816(acc[mi][ni], al[mi], bhp);
                }
        }
        __syncthreads();
    }

    const int erow = (lane >> 2);
    const int ecol = (lane & 3) * 2;
    #pragma unroll
    for (int mi = 0; mi < 4; ++mi){
        #pragma unroll
        for (int ni = 0; ni < 4; ++ni){
            const int gm = m0 + wm + mi*16 + erow;
            const int gn = n0 + wn + ni*8 + ecol;
            *(float2*)(C + (size_t)gm*N + gn)     = make_float2(acc[mi][ni][0], acc[mi][ni][1]);
            *(float2*)(C + (size_t)(gm+8)*N + gn) = make_float2(acc[mi][ni][2], acc[mi][ni][3]);
        }
    }
}

__global__ __launch_bounds__(256, 2) void gemm_qkv_kernel(){
    gemm_bf16x3_body(g_xh, g_xl, g_wqkvh, g_wqkvl, g_qkv, QKV_OUT, GD);
}
__global__ __launch_bounds__(256, 2) void gemm_out_kernel(float* __restrict__ out){
    gemm_bf16x3_body(g_attnh, g_attnl, g_woh, g_wol, out, GD, GD);
}

// ---------------- RoPE (+ fold attention scale into q) ----------------
__global__ void rope_kernel(){
    const int row = blockIdx.x;
    const float fpos = (float)(row & (GS-1));
    const float SCL = 0.08838834764831845f;   // 1/sqrt(128)
    float* base = g_qkv + (size_t)row * QKV_OUT;
    for (int it = threadIdx.x; it < 40*64; it += blockDim.x){
        const int hh = it >> 6;
        const int i  = it & 63;
        float* p = base + (hh < GH ? hh*GHD : GH*GHD + (hh-GH)*GHD);
        const float inv = powf(500000.0f, -(float)i * (1.0f/64.0f));
        const float fr  = fpos * inv;
        float sn, cs;
        sincosf(fr, &sn, &cs);
        const float x1 = p[i], x2 = p[i+64];
        float r1 = x1*cs - x2*sn;
        float r2 = x2*cs + x1*sn;
        if (hh < GH){ r1 *= SCL; r2 *= SCL; }
        p[i]    = r1;
        p[i+64] = r2;
    }
}

// ---------------- HMMA flash attention (bf16x3, causal, GQA 4:1) ----------------
// Q tile 128 rows, K tile 64, hd 128. 8 warps, warp = 16 q rows.
#define PQ 272
#define PK 272
#define PV 144
#define SQ_BYTES (128*PQ)                    // 34816 (x2 hi/lo)
#define SK_BYTES (64*PK)                     // 17408
#define SV_BYTES (128*PV)                    // 18432
#define KV_STAGE (2*SK_BYTES + 2*SV_BYTES)   // 71680
#define ATT_SMEM (2*SQ_BYTES + 2*KV_STAGE)   // 212992

__global__ __launch_bounds__(256, 1) void attn_mma_kernel(){
    extern __shared__ __align__(16) char smraw[];
    const uint32_t sb = smem_u32(smraw);
    const int tid  = threadIdx.x;
    const int w    = tid >> 5;
    const int lane = tid & 31;
    const int qt = blockIdx.x, h = blockIdx.y, b = blockIdx.z;
    const int kh = h >> 2;

    const __nv_bfloat16* qhB = g_qkh + (size_t)(b*GS)*QKSTRIDE + h*GHD;
    const __nv_bfloat16* qlB = g_qkl + (size_t)(b*GS)*QKSTRIDE + h*GHD;
    const __nv_bfloat16* khB = g_qkh + (size_t)(b*GS)*QKSTRIDE + GD + kh*GHD;
    const __nv_bfloat16* klB = g_qkl + (size_t)(b*GS)*QKSTRIDE + GD + kh*GHD;
    const __nv_bfloat16* vhB = g_vth + (size_t)((b*GKH + kh)*GHD)*GS;
    const __nv_bfloat16* vlB = g_vtl + (size_t)((b*GKH + kh)*GHD)*GS;

    // Q tile load (one group)
    #pragma unroll
    for (int p = 0; p < 16; ++p){
        const int idx  = p*256 + tid;
        const int part = idx >> 11;
        const int rem  = idx & 2047;
        const int row  = rem >> 4;
        const int ch   = rem & 15;
        const __nv_bfloat16* src = (part ? qlB : qhB) + (size_t)(qt*128 + row)*QKSTRIDE + ch*8;
        cp16(sb + (uint32_t)(part*SQ_BYTES + row*PQ + ch*16), src);
    }
    cp_commit();

    auto issue_kv = [&](int kt){
        const uint32_t stg = sb + 2*SQ_BYTES + (uint32_t)((kt & 1) * KV_STAGE);
        #pragma unroll
        for (int p = 0; p < 16; ++p){
            const int idx = p*256 + tid;
            if (idx < 2048){
                const int part = idx >> 10;
                const int rem  = idx & 1023;
                const int row  = rem >> 4;
                const int ch   = rem & 15;
                const __nv_bfloat16* src = (part ? klB : khB) + (size_t)(kt*64 + row)*QKSTRIDE + ch*8;
                cp16(stg + (uint32_t)(part*SK_BYTES + row*PK + ch*16), src);
            } else {
                const int j    = idx - 2048;
                const int part = j >> 10;
                const int rem  = j & 1023;
                const int row  = rem >> 3;
                const int ch   = rem & 7;
                const __nv_bfloat16* src = (part ? vlB : vhB) + (size_t)row*GS + kt*64 + ch*8;
                cp16(stg + (uint32_t)(2*SK_BYTES + part*SV_BYTES + row*PV + ch*16), src);
            }
        }
        cp_commit();
    };

    issue_kv(0);

    const int arow = w*16 + (lane & 15);
    const int akb  = (lane >> 4) * 16;
    const int brow = (lane & 7) + ((lane >> 4) << 3);
    const int bkb  = ((lane >> 3) & 1) * 16;

    float oacc[16][4];
    #pragma unroll
    for (int i = 0; i < 16; ++i)
        #pragma unroll
        for (int c = 0; c < 4; ++c) oacc[i][c] = 0.f;
    float mr0 = -1e30f, mr1 = -1e30f, lr0 = 0.f, lr1 = 0.f;

    const int mx = 2*qt + 1;
    for (int kt = 0; kt <= mx; ++kt){
        cp_wait<0>();
        __syncthreads();
        if (kt < mx) issue_kv(kt+1);
        const uint32_t stg = sb + 2*SQ_BYTES + (uint32_t)((kt & 1) * KV_STAGE);

        // ---- S = Q K^T (bf16x3) ----
        float sacc[8][4];
        #pragma unroll
        for (int nf = 0; nf < 8; ++nf)
            #pragma unroll
            for (int c = 0; c < 4; ++c) sacc[nf][c] = 0.f;

        #pragma unroll
        for (int ks = 0; ks < 8; ++ks){
            uint32_t qh_t[4], ql_t[4];
            const uint32_t qa = sb + (uint32_t)(arow*PQ + ks*32 + akb);
            ldmx4(qh_t, qa);
            ldmx4(ql_t, qa + SQ_BYTES);
            uint32_t kfh[4][4], kfl[4][4];
            #pragma unroll
            for (int n4 = 0; n4 < 4; ++n4){
                const uint32_t ka = stg + (uint32_t)((brow + n4*16)*PK + ks*32 + bkb);
                ldmx4(kfh[n4], ka);
                ldmx4(kfl[n4], ka + SK_BYTES);
            }
            #pragma unroll
            for (int nf = 0; nf < 8; ++nf){
                const uint32_t* bh = &kfh[nf>>1][(nf&1)*2];
                const uint32_t* bl = &kfl[nf>>1][(nf&1)*2];
                mma16816(sacc[nf], qh_t, bh);
                mma16816(sacc[nf], qh_t, bl);
                mma16816(sacc[nf], ql_t, bh);
            }
        }

        // ---- causal mask (only diag-region k tiles) ----
        if (kt >= 2*qt){
            const int r0 = qt*128 + w*16 + (lane >> 2);
            const int cb = kt*64 + (lane & 3)*2;
            #pragma unroll
            for (int nf = 0; nf < 8; ++nf){
                const int c = cb + nf*8;
                if (c     > r0)     sacc[nf][0] = -1e30f;
                if (c + 1 > r0)     sacc[nf][1] = -1e30f;
                if (c     > r0 + 8) sacc[nf][2] = -1e30f;
                if (c + 1 > r0 + 8) sacc[nf][3] = -1e30f;
            }
        }

        // ---- online softmax ----
        float rm0 = -1e30f, rm1 = -1e30f;
        #pragma unroll
        for (int nf = 0; nf < 8; ++nf){
            rm0 = fmaxf(rm0, fmaxf(sacc[nf][0], sacc[nf][1]));
            rm1 = fmaxf(rm1, fmaxf(sacc[nf][2], sacc[nf][3]));
        }
        rm0 = fmaxf(rm0, __shfl_xor_sync(0xffffffffu, rm0, 1));
        rm0 = fmaxf(rm0, __shfl_xor_sync(0xffffffffu, rm0, 2));
        rm1 = fmaxf(rm1, __shfl_xor_sync(0xffffffffu, rm1, 1));
        rm1 = fmaxf(rm1, __shfl_xor_sync(0xffffffffu, rm1, 2));
        const float mn0 = fmaxf(mr0, rm0);
        const float mn1 = fmaxf(mr1, rm1);
        const float a0 = __expf(mr0 - mn0);
        const float a1 = __expf(mr1 - mn1);
        float ps0 = 0.f, ps1 = 0.f;
        #pragma unroll
        for (int nf = 0; nf < 8; ++nf){
            sacc[nf][0] = __expf(sacc[nf][0] - mn0); ps0 += sacc[nf][0];
            sacc[nf][1] = __expf(sacc[nf][1] - mn0); ps0 += sacc[nf][1];
            sacc[nf][2] = __expf(sacc[nf][2] - mn1); ps1 += sacc[nf][2];
            sacc[nf][3] = __expf(sacc[nf][3] - mn1); ps1 += sacc[nf][3];
        }
        ps0 += __shfl_xor_sync(0xffffffffu, ps0, 1);
        ps0 += __shfl_xor_sync(0xffffffffu, ps0, 2);
        ps1 += __shfl_xor_sync(0xffffffffu, ps1, 1);
        ps1 += __shfl_xor_sync(0xffffffffu, ps1, 2);
        lr0 = lr0*a0 + ps0;  mr0 = mn0;
        lr1 = lr1*a1 + ps1;  mr1 = mn1;
        #pragma unroll
        for (int nf = 0; nf < 16; ++nf){
            oacc[nf][0] *= a0; oacc[nf][1] *= a0;
            oacc[nf][2] *= a1; oacc[nf][3] *= a1;
        }

        // ---- O += P V (bf16x3, Vt col-major) ----
        #pragma unroll
        for (int ks = 0; ks < 4; ++ks){
            uint32_t pah[4], pal[4];
            packhl(sacc[2*ks][0],   sacc[2*ks][1],   pah[0], pal[0]);
            packhl(sacc[2*ks][2],   sacc[2*ks][3],   pah[1], pal[1]);
            packhl(sacc[2*ks+1][0], sacc[2*ks+1][1], pah[2], pal[2]);
            packhl(sacc[2*ks+1][2], sacc[2*ks+1][3], pah[3], pal[3]);
            #pragma unroll
            for (int nd2 = 0; nd2 < 8; ++nd2){
                uint32_t vfh[4], vfl[4];
                const uint32_t va = stg + (uint32_t)(2*SK_BYTES + (brow + nd2*16)*PV + ks*32 + bkb);
                ldmx4(vfh, va);
                ldmx4(vfl, va + SV_BYTES);
                mma16816(oacc[nd2*2],   pah, &vfh[0]);
                mma16816(oacc[nd2*2],   pah, &vfl[0]);
                mma16816(oacc[nd2*2],   pal, &vfh[0]);
                mma16816(oacc[nd2*2+1], pah, &vfh[2]);
                mma16816(oacc[nd2*2+1], pah, &vfl[2]);
                mma16816(oacc[nd2*2+1], pal, &vfh[2]);
            }
        }
    }

    // ---- epilogue: O /= l, write bf16 hi/lo for the out-proj GEMM ----
    const float i0 = 1.f / lr0;
    const float i1 = 1.f / lr1;
    const int gr0 = b*GS + qt*128 + w*16 + (lane >> 2);
    const int cb  = h*GHD + (lane & 3)*2;
    #pragma unroll
    for (int nf = 0; nf < 16; ++nf){
        const float v0 = oacc[nf][0]*i0, v1 = oacc[nf][1]*i0;
        const float v2 = oacc[nf][2]*i1, v3 = oacc[nf][3]*i1;
        uint32_t h01, l01, h23, l23;
        packhl(v0, v1, h01, l01);
        packhl(v2, v3, h23, l23);
        const size_t o0 = (size_t)gr0*GD + cb + nf*8;
        const size_t o1 = (size_t)(gr0+8)*GD + cb + nf*8;
        *(uint32_t*)(g_attnh + o0) = h01;
        *(uint32_t*)(g_attnl + o0) = l01;
        *(uint32_t*)(g_attnh + o1) = h23;
        *(uint32_t*)(g_attnl + o1) = l23;
    }
}

// ---------------- launch ----------------
extern "C" void kernel_launch(void* const* d_in, const int* in_sizes, int n_in,
                              void* d_out, int out_size)
{
    const float* x    = (const float*)d_in[0];
    const float* Wqkv = (const float*)d_in[1];
    const float* Wo   = (const float*)d_in[2];
    float* out = (float*)d_out;

    cudaFuncSetAttribute(gemm_qkv_kernel, cudaFuncAttributeMaxDynamicSharedMemorySize, GEMM_SMEM);
    cudaFuncSetAttribute(gemm_out_kernel, cudaFuncAttributeMaxDynamicSharedMemorySize, GEMM_SMEM);
    cudaFuncSetAttribute(attn_mma_kernel, cudaFuncAttributeMaxDynamicSharedMemorySize, ATT_SMEM);

    unsigned long long *xh, *xl, *wqh, *wql, *woh, *wol;
    cudaGetSymbolAddress((void**)&xh,  g_xh);
    cudaGetSymbolAddress((void**)&xl,  g_xl);
    cudaGetSymbolAddress((void**)&wqh, g_wqkvh);
    cudaGetSymbolAddress((void**)&wql, g_wqkvl);
    cudaGetSymbolAddress((void**)&woh, g_woh);
    cudaGetSymbolAddress((void**)&wol, g_wol);

    const int nx  = GB*GS*GD/4;
    const int nwq = QKV_OUT*GD/4;
    const int nwo = GD*GD/4;
    cvt_pair_kernel<<<(nx +255)/256, 256>>>((const float4*)x,    xh,  xl,  nx);
    cvt_pair_kernel<<<(nwq+255)/256, 256>>>((const float4*)Wqkv, wqh, wql, nwq);
    cvt_pair_kernel<<<(nwo+255)/256, 256>>>((const float4*)Wo,   woh, wol, nwo);

    dim3 g1(QKV_OUT/128, (GB*GS)/128);
    gemm_qkv_kernel<<<g1, 256, GEMM_SMEM>>>();

    rope_kernel<<<GB*GS, 256>>>();

    const int nqk = GB*GS*QKSTRIDE/4;
    qkconv_kernel<<<(nqk+255)/256, 256>>>();
    dim3 gv(GS/32, GHD/32, GB*GKH);
    vconv_kernel<<<gv, dim3(32,8)>>>();

    dim3 ga(GS/128, GH, GB);
    attn_mma_kernel<<<ga, 256, ATT_SMEM>>>();

    dim3 g2(GD/128, (GB*GS)/128);
    gemm_out_kernel<<<g2, 256, GEMM_SMEM>>>(out);
}

// round 8
// speedup vs baseline: 3.1223x; 1.0003x over previous
#include <cuda_runtime.h>
#include <cuda_bf16.h>
#include <math.h>
#include <stdint.h>

// ---------------- problem constants ----------------
#define GB   2
#define GS   2048
#define GD   4096
#define GH   32
#define GKH  8
#define GHD  128
#define QKV_OUT 6144
#define QKSTRIDE 5120     // q(4096) + k(1024) packed

// ---------------- device scratch ----------------
__device__ float g_qkv[GB*GS*QKV_OUT];                       // fp32 qkv (gemm out, rope)
__device__ __nv_bfloat16 g_xh[GB*GS*GD],      g_xl[GB*GS*GD];
__device__ __nv_bfloat16 g_wqkvh[QKV_OUT*GD], g_wqkvl[QKV_OUT*GD];
__device__ __nv_bfloat16 g_woh[GD*GD],        g_wol[GD*GD];
__device__ __nv_bfloat16 g_attnh[GB*GS*GD],   g_attnl[GB*GS*GD];
__device__ __nv_bfloat16 g_qkh[GB*GS*QKSTRIDE], g_qkl[GB*GS*QKSTRIDE];   // roped q(scaled)+k, bf16 hi/lo
__device__ __nv_bfloat16 g_vth[GB*GKH*GHD*GS],  g_vtl[GB*GKH*GHD*GS];    // V transposed [b,kh,d,s]

// ---------------- smem addr helper ----------------
__device__ __forceinline__ uint32_t smem_u32(const void* p){
    uint32_t a;
    asm("{ .reg .u64 t; cvta.to.shared.u64 t, %1; cvt.u32.u64 %0, t; }" : "=r"(a) : "l"(p));
    return a;
}

// ---------------- HMMA / cp.async helpers ----------------
__device__ __forceinline__ void ldmx4(uint32_t* r, uint32_t addr){
    asm volatile("ldmatrix.sync.aligned.m8n8.x4.shared.b16 {%0,%1,%2,%3}, [%4];"
        : "=r"(r[0]), "=r"(r[1]), "=r"(r[2]), "=r"(r[3]) : "r"(addr));
}
__device__ __forceinline__ void mma16816(float* c, const uint32_t* a, const uint32_t* b){
    asm volatile(
        "mma.sync.aligned.m16n8k16.row.col.f32.bf16.bf16.f32 "
        "{%0,%1,%2,%3}, {%4,%5,%6,%7}, {%8,%9}, {%0,%1,%2,%3};"
        : "+f"(c[0]), "+f"(c[1]), "+f"(c[2]), "+f"(c[3])
        : "r"(a[0]), "r"(a[1]), "r"(a[2]), "r"(a[3]), "r"(b[0]), "r"(b[1]));
}
__device__ __forceinline__ void cp16(uint32_t saddr, const void* g){
    asm volatile("cp.async.cg.shared.global [%0], [%1], 16;"
        :: "r"(saddr), "l"(__cvta_generic_to_global(g)) : "memory");
}
__device__ __forceinline__ void cp_commit(){
    asm volatile("cp.async.commit_group;" ::: "memory");
}
template <int N>
__device__ __forceinline__ void cp_wait(){
    asm volatile("cp.async.wait_group %0;" :: "n"(N) : "memory");
}

// ---------------- bf16 hi/lo helpers ----------------
__device__ __forceinline__ void hilo4(float4 v, unsigned long long& h, unsigned long long& l){
    __nv_bfloat16 h0 = __float2bfloat16(v.x);
    __nv_bfloat16 h1 = __float2bfloat16(v.y);
    __nv_bfloat16 h2 = __float2bfloat16(v.z);
    __nv_bfloat16 h3 = __float2bfloat16(v.w);
    __nv_bfloat16 l0 = __float2bfloat16(v.x - __bfloat162float(h0));
    __nv_bfloat16 l1 = __float2bfloat16(v.y - __bfloat162float(h1));
    __nv_bfloat16 l2 = __float2bfloat16(v.z - __bfloat162float(h2));
    __nv_bfloat16 l3 = __float2bfloat16(v.w - __bfloat162float(h3));
    h = (unsigned long long)__bfloat16_as_ushort(h0)
      | ((unsigned long long)__bfloat16_as_ushort(h1) << 16)
      | ((unsigned long long)__bfloat16_as_ushort(h2) << 32)
      | ((unsigned long long)__bfloat16_as_ushort(h3) << 48);
    l = (unsigned long long)__bfloat16_as_ushort(l0)
      | ((unsigned long long)__bfloat16_as_ushort(l1) << 16)
      | ((unsigned long long)__bfloat16_as_ushort(l2) << 32)
      | ((unsigned long long)__bfloat16_as_ushort(l3) << 48);
}
__device__ __forceinline__ void packhl(float f0, float f1, uint32_t& h, uint32_t& l){
    __nv_bfloat16 h0 = __float2bfloat16(f0);
    __nv_bfloat16 h1 = __float2bfloat16(f1);
    __nv_bfloat16 b0 = __float2bfloat16(f0 - __bfloat162float(h0));
    __nv_bfloat16 b1 = __float2bfloat16(f1 - __bfloat162float(h1));
    h = (uint32_t)__bfloat16_as_ushort(h0) | ((uint32_t)__bfloat16_as_ushort(h1) << 16);
    l = (uint32_t)__bfloat16_as_ushort(b0) | ((uint32_t)__bfloat16_as_ushort(b1) << 16);
}

// ---------------- fp32 -> bf16 hi/lo (same layout) ----------------
__global__ __launch_bounds__(256) void cvt_pair_kernel(const float4* __restrict__ src,
                                                       unsigned long long* __restrict__ h,
                                                       unsigned long long* __restrict__ l,
                                                       int n4){
    const int i = blockIdx.x*blockDim.x + threadIdx.x;
    if (i < n4){
        unsigned long long hh, ll;
        hilo4(src[i], hh, ll);
        h[i] = hh;
        l[i] = ll;
    }
}

// ---------------- q+k region -> bf16 hi/lo (6144 stride -> 5120 stride) ----------------
__global__ __launch_bounds__(256) void qkconv_kernel(){
    const int i = blockIdx.x*blockDim.x + threadIdx.x;   // over B*S*5120/4
    const int n4 = GB*GS*QKSTRIDE/4;
    if (i >= n4) return;
    const int row = i / (QKSTRIDE/4);
    const int c   = i - row*(QKSTRIDE/4);
    const float4 v = *(const float4*)(g_qkv + (size_t)row*QKV_OUT + c*4);
    unsigned long long h, l;
    hilo4(v, h, l);
    *(unsigned long long*)(g_qkh + (size_t)row*QKSTRIDE + c*4) = h;
    *(unsigned long long*)(g_qkl + (size_t)row*QKSTRIDE + c*4) = l;
}

// ---------------- V transpose conversion: [b,s,kh,d] -> [b,kh,d,s] bf16 hi/lo ----------------
__global__ void vconv_kernel(){
    __shared__ float t[32][33];
    const int s0 = blockIdx.x*32;
    const int d0 = blockIdx.y*32;
    const int bkh = blockIdx.z;           // b*8+kh
    const int b  = bkh >> 3, kh = bkh & 7;
    #pragma unroll
    for (int i = 0; i < 4; ++i){
        const int s = s0 + threadIdx.y + i*8;
        const int d = d0 + threadIdx.x;
        t[threadIdx.y + i*8][threadIdx.x] =
            g_qkv[(size_t)(b*GS + s)*QKV_OUT + QKSTRIDE + kh*GHD + d];
    }
    __syncthreads();
    #pragma unroll
    for (int i = 0; i < 4; ++i){
        const int d = d0 + threadIdx.y + i*8;
        const int s = s0 + threadIdx.x;
        const float v = t[threadIdx.x][threadIdx.y + i*8];
        const __nv_bfloat16 h = __float2bfloat16(v);
        const __nv_bfloat16 l = __float2bfloat16(v - __bfloat162float(h));
        const size_t o = ((size_t)(bkh*GHD + d))*GS + s;
        g_vth[o] = h;
        g_vtl[o] = l;
    }
}

// ---------------- HMMA bf16x3 GEMM, 2-stage cp.async, 2 CTAs/SM ----------------
#define GP   80
#define TB   10240          // 128*80
#define STG  (4*TB)         // Ah,Al,Bh,Bl
#define GEMM_SMEM (2*STG)   // 81920

__device__ __forceinline__ void gemm_bf16x3_body(
    const __nv_bfloat16* __restrict__ Ah, const __nv_bfloat16* __restrict__ Al,
    const __nv_bfloat16* __restrict__ Bh, const __nv_bfloat16* __restrict__ Bl,
    float* __restrict__ C, int N, int K)
{
    extern __shared__ __align__(16) char dyn[];
    const uint32_t sb = smem_u32(dyn);

    const int tid  = threadIdx.x;
    const int wid  = tid >> 5;
    const int lane = tid & 31;
    const int wm   = (wid & 1) * 64;
    const int wn   = (wid >> 1) * 32;
    const int m0   = blockIdx.y * 128;
    const int n0   = blockIdx.x * 128;

    const __nv_bfloat16* gbase[4] = {
        Ah + (size_t)m0*K, Al + (size_t)m0*K,
        Bh + (size_t)n0*K, Bl + (size_t)n0*K
    };
    const int r0  = tid >> 2;
    const int c16 = tid & 3;

    auto issue = [&](int s, int k0){
        const uint32_t stg = sb + (uint32_t)(s*STG);
        #pragma unroll
        for (int p = 0; p < 8; ++p){
            const int t   = p >> 1;
            const int row = (p & 1)*64 + r0;
            cp16(stg + (uint32_t)(t*TB + row*GP + c16*16),
                 gbase[t] + (size_t)row*K + k0 + c16*8);
        }
        cp_commit();
    };

    float acc[4][4][4];
    #pragma unroll
    for (int i=0;i<4;i++)
        #pragma unroll
        for (int j=0;j<4;j++)
            #pragma unroll
            for (int c=0;c<4;c++) acc[i][j][c] = 0.f;

    const int NIT = K / 32;
    issue(0, 0);

    const int arow = wm + (lane & 15);
    const int akb  = (lane >> 4) * 16;
    const int brow = wn + (lane & 7) + ((lane >> 4) << 3);
    const int bkb  = ((lane >> 3) & 1) * 16;

    for (int it = 0; it < NIT; ++it){
        cp_wait<0>();
        __syncthreads();
        if (it + 1 < NIT) issue((it+1) & 1, (it+1)*32);

        const uint32_t stage = sb + (uint32_t)((it & 1) * STG);
        #pragma unroll
        for (int ks = 0; ks < 2; ++ks){
            uint32_t ah[4][4], al[4][4], bh[2][4], bl[2][4];
            #pragma unroll
            for (int mi = 0; mi < 4; ++mi){
                const uint32_t ad = stage + (uint32_t)((arow + mi*16)*GP + ks*32 + akb);
                ldmx4(ah[mi], ad);
                ldmx4(al[mi], ad + TB);
            }
            #pragma unroll
            for (int n2 = 0; n2 < 2; ++n2){
                const uint32_t bd = stage + (uint32_t)(2*TB + (brow + n2*16)*GP + ks*32 + bkb);
                ldmx4(bh[n2], bd);
                ldmx4(bl[n2], bd + TB);
            }
            #pragma unroll
            for (int mi = 0; mi < 4; ++mi)
                #pragma unroll
                for (int ni = 0; ni < 4; ++ni){
                    const uint32_t* bhp = &bh[ni>>1][(ni&1)*2];
                    const uint32_t* blp = &bl[ni>>1][(ni&1)*2];
                    mma16816(acc[mi][ni], ah[mi], bhp);
                    mma16816(acc[mi][ni], ah[mi], blp);
                    mma16816(acc[mi][ni], al[mi], bhp);
                }
        }
        __syncthreads();
    }

    const int erow = (lane >> 2);
    const int ecol = (lane & 3) * 2;
    #pragma unroll
    for (int mi = 0; mi < 4; ++mi){
        #pragma unroll
        for (int ni = 0; ni < 4; ++ni){
            const int gm = m0 + wm + mi*16 + erow;
            const int gn = n0 + wn + ni*8 + ecol;
            *(float2*)(C + (size_t)gm*N + gn)     = make_float2(acc[mi][ni][0], acc[mi][ni][1]);
            *(float2*)(C + (size_t)(gm+8)*N + gn) = make_float2(acc[mi][ni][2], acc[mi][ni][3]);
        }
    }
}

__global__ __launch_bounds__(256, 2) void gemm_qkv_kernel(){
    gemm_bf16x3_body(g_xh, g_xl, g_wqkvh, g_wqkvl, g_qkv, QKV_OUT, GD);
}
__global__ __launch_bounds__(256, 2) void gemm_out_kernel(float* __restrict__ out){
    gemm_bf16x3_body(g_attnh, g_attnl, g_woh, g_wol, out, GD, GD);
}

// ---------------- RoPE (+ fold attention scale into q) ----------------
__global__ void rope_kernel(){
    const int row = blockIdx.x;
    const float fpos = (float)(row & (GS-1));
    const float SCL = 0.08838834764831845f;   // 1/sqrt(128)
    float* base = g_qkv + (size_t)row * QKV_OUT;
    for (int it = threadIdx.x; it < 40*64; it += blockDim.x){
        const int hh = it >> 6;
        const int i  = it & 63;
        float* p = base + (hh < GH ? hh*GHD : GH*GHD + (hh-GH)*GHD);
        const float inv = powf(500000.0f, -(float)i * (1.0f/64.0f));
        const float fr  = fpos * inv;
        float sn, cs;
        sincosf(fr, &sn, &cs);
        const float x1 = p[i], x2 = p[i+64];
        float r1 = x1*cs - x2*sn;
        float r2 = x2*cs + x1*sn;
        if (hh < GH){ r1 *= SCL; r2 *= SCL; }
        p[i]    = r1;
        p[i+64] = r2;
    }
}

// ---------------- HMMA flash attention (bf16x3, causal, GQA 4:1) ----------------
// Q tile 128 rows, K tile 64, hd 128. 8 warps, warp = 16 q rows.
#define PQ 272
#define PK 272
#define PV 144
#define SQ_BYTES (128*PQ)                    // 34816 (x2 hi/lo)
#define SK_BYTES (64*PK)                     // 17408
#define SV_BYTES (128*PV)                    // 18432
#define KV_STAGE (2*SK_BYTES + 2*SV_BYTES)   // 71680
#define ATT_SMEM (2*SQ_BYTES + 2*KV_STAGE)   // 212992

__global__ __launch_bounds__(256, 1) void attn_mma_kernel(){
    extern __shared__ __align__(16) char smraw[];
    const uint32_t sb = smem_u32(smraw);
    const int tid  = threadIdx.x;
    const int w    = tid >> 5;
    const int lane = tid & 31;
    const int qt = blockIdx.x, h = blockIdx.y, b = blockIdx.z;
    const int kh = h >> 2;

    const __nv_bfloat16* qhB = g_qkh + (size_t)(b*GS)*QKSTRIDE + h*GHD;
    const __nv_bfloat16* qlB = g_qkl + (size_t)(b*GS)*QKSTRIDE + h*GHD;
    const __nv_bfloat16* khB = g_qkh + (size_t)(b*GS)*QKSTRIDE + GD + kh*GHD;
    const __nv_bfloat16* klB = g_qkl + (size_t)(b*GS)*QKSTRIDE + GD + kh*GHD;
    const __nv_bfloat16* vhB = g_vth + (size_t)((b*GKH + kh)*GHD)*GS;
    const __nv_bfloat16* vlB = g_vtl + (size_t)((b*GKH + kh)*GHD)*GS;

    // Q tile load (one group)
    #pragma unroll
    for (int p = 0; p < 16; ++p){
        const int idx  = p*256 + tid;
        const int part = idx >> 11;
        const int rem  = idx & 2047;
        const int row  = rem >> 4;
        const int ch   = rem & 15;
        const __nv_bfloat16* src = (part ? qlB : qhB) + (size_t)(qt*128 + row)*QKSTRIDE + ch*8;
        cp16(sb + (uint32_t)(part*SQ_BYTES + row*PQ + ch*16), src);
    }
    cp_commit();

    auto issue_kv = [&](int kt){
        const uint32_t stg = sb + 2*SQ_BYTES + (uint32_t)((kt & 1) * KV_STAGE);
        #pragma unroll
        for (int p = 0; p < 16; ++p){
            const int idx = p*256 + tid;
            if (idx < 2048){
                const int part = idx >> 10;
                const int rem  = idx & 1023;
                const int row  = rem >> 4;
                const int ch   = rem & 15;
                const __nv_bfloat16* src = (part ? klB : khB) + (size_t)(kt*64 + row)*QKSTRIDE + ch*8;
                cp16(stg + (uint32_t)(part*SK_BYTES + row*PK + ch*16), src);
            } else {
                const int j    = idx - 2048;
                const int part = j >> 10;
                const int rem  = j & 1023;
                const int row  = rem >> 3;
                const int ch   = rem & 7;
                const __nv_bfloat16* src = (part ? vlB : vhB) + (size_t)row*GS + kt*64 + ch*8;
                cp16(stg + (uint32_t)(2*SK_BYTES + part*SV_BYTES + row*PV + ch*16), src);
            }
        }
        cp_commit();
    };

    issue_kv(0);

    const int arow = w*16 + (lane & 15);
    const int akb  = (lane >> 4) * 16;
    const int brow = (lane & 7) + ((lane >> 4) << 3);
    const int bkb  = ((lane >> 3) & 1) * 16;

    float oacc[16][4];
    #pragma unroll
    for (int i = 0; i < 16; ++i)
        #pragma unroll
        for (int c = 0; c < 4; ++c) oacc[i][c] = 0.f;
    float mr0 = -1e30f, mr1 = -1e30f, lr0 = 0.f, lr1 = 0.f;

    const int mx = 2*qt + 1;
    for (int kt = 0; kt <= mx; ++kt){
        cp_wait<0>();
        __syncthreads();
        if (kt < mx) issue_kv(kt+1);
        const uint32_t stg = sb + 2*SQ_BYTES + (uint32_t)((kt & 1) * KV_STAGE);

        // ---- S = Q K^T (bf16x3) ----
        float sacc[8][4];
        #pragma unroll
        for (int nf = 0; nf < 8; ++nf)
            #pragma unroll
            for (int c = 0; c < 4; ++c) sacc[nf][c] = 0.f;

        #pragma unroll
        for (int ks = 0; ks < 8; ++ks){
            uint32_t qh_t[4], ql_t[4];
            const uint32_t qa = sb + (uint32_t)(arow*PQ + ks*32 + akb);
            ldmx4(qh_t, qa);
            ldmx4(ql_t, qa + SQ_BYTES);
            uint32_t kfh[4][4], kfl[4][4];
            #pragma unroll
            for (int n4 = 0; n4 < 4; ++n4){
                const uint32_t ka = stg + (uint32_t)((brow + n4*16)*PK + ks*32 + bkb);
                ldmx4(kfh[n4], ka);
                ldmx4(kfl[n4], ka + SK_BYTES);
            }
            #pragma unroll
            for (int nf = 0; nf < 8; ++nf){
                const uint32_t* bh = &kfh[nf>>1][(nf&1)*2];
                const uint32_t* bl = &kfl[nf>>1][(nf&1)*2];
                mma16816(sacc[nf], qh_t, bh);
                mma16816(sacc[nf], qh_t, bl);
                mma16816(sacc[nf], ql_t, bh);
            }
        }

        // ---- causal mask (only diag-region k tiles) ----
        if (kt >= 2*qt){
            const int r0 = qt*128 + w*16 + (lane >> 2);
            const int cb = kt*64 + (lane & 3)*2;
            #pragma unroll
            for (int nf = 0; nf < 8; ++nf){
                const int c = cb + nf*8;
                if (c     > r0)     sacc[nf][0] = -1e30f;
                if (c + 1 > r0)     sacc[nf][1] = -1e30f;
                if (c     > r0 + 8) sacc[nf][2] = -1e30f;
                if (c + 1 > r0 + 8) sacc[nf][3] = -1e30f;
            }
        }

        // ---- online softmax ----
        float rm0 = -1e30f, rm1 = -1e30f;
        #pragma unroll
        for (int nf = 0; nf < 8; ++nf){
            rm0 = fmaxf(rm0, fmaxf(sacc[nf][0], sacc[nf][1]));
            rm1 = fmaxf(rm1, fmaxf(sacc[nf][2], sacc[nf][3]));
        }
        rm0 = fmaxf(rm0, __shfl_xor_sync(0xffffffffu, rm0, 1));
        rm0 = fmaxf(rm0, __shfl_xor_sync(0xffffffffu, rm0, 2));
        rm1 = fmaxf(rm1, __shfl_xor_sync(0xffffffffu, rm1, 1));
        rm1 = fmaxf(rm1, __shfl_xor_sync(0xffffffffu, rm1, 2));
        const float mn0 = fmaxf(mr0, rm0);
        const float mn1 = fmaxf(mr1, rm1);
        const float a0 = __expf(mr0 - mn0);
        const float a1 = __expf(mr1 - mn1);
        float ps0 = 0.f, ps1 = 0.f;
        #pragma unroll
        for (int nf = 0; nf < 8; ++nf){
            sacc[nf][0] = __expf(sacc[nf][0] - mn0); ps0 += sacc[nf][0];
            sacc[nf][1] = __expf(sacc[nf][1] - mn0); ps0 += sacc[nf][1];
            sacc[nf][2] = __expf(sacc[nf][2] - mn1); ps1 += sacc[nf][2];
            sacc[nf][3] = __expf(sacc[nf][3] - mn1); ps1 += sacc[nf][3];
        }
        ps0 += __shfl_xor_sync(0xffffffffu, ps0, 1);
        ps0 += __shfl_xor_sync(0xffffffffu, ps0, 2);
        ps1 += __shfl_xor_sync(0xffffffffu, ps1, 1);
        ps1 += __shfl_xor_sync(0xffffffffu, ps1, 2);
        lr0 = lr0*a0 + ps0;  mr0 = mn0;
        lr1 = lr1*a1 + ps1;  mr1 = mn1;
        #pragma unroll
        for (int nf = 0; nf < 16; ++nf){
            oacc[nf][0] *= a0; oacc[nf][1] *= a0;
            oacc[nf][2] *= a1; oacc[nf][3] *= a1;
        }

        // ---- O += P V (bf16x3, Vt col-major) ----
        #pragma unroll
        for (int ks = 0; ks < 4; ++ks){
            uint32_t pah[4], pal[4];
            packhl(sacc[2*ks][0],   sacc[2*ks][1],   pah[0], pal[0]);
            packhl(sacc[2*ks][2],   sacc[2*ks][3],   pah[1], pal[1]);
            packhl(sacc[2*ks+1][0], sacc[2*ks+1][1], pah[2], pal[2]);
            packhl(sacc[2*ks+1][2], sacc[2*ks+1][3], pah[3], pal[3]);
            #pragma unroll
            for (int nd2 = 0; nd2 < 8; ++nd2){
                uint32_t vfh[4], vfl[4];
                const uint32_t va = stg + (uint32_t)(2*SK_BYTES + (brow + nd2*16)*PV + ks*32 + bkb);
                ldmx4(vfh, va);
                ldmx4(vfl, va + SV_BYTES);
                mma16816(oacc[nd2*2],   pah, &vfh[0]);
                mma16816(oacc[nd2*2],   pah, &vfl[0]);
                mma16816(oacc[nd2*2],   pal, &vfh[0]);
                mma16816(oacc[nd2*2+1], pah, &vfh[2]);
                mma16816(oacc[nd2*2+1], pah, &vfl[2]);
                mma16816(oacc[nd2*2+1], pal, &vfh[2]);
            }
        }
    }

    // ---- epilogue: O /= l, write bf16 hi/lo for the out-proj GEMM ----
    const float i0 = 1.f / lr0;
    const float i1 = 1.f / lr1;
    const int gr0 = b*GS + qt*128 + w*16 + (lane >> 2);
    const int cb  = h*GHD + (lane & 3)*2;
    #pragma unroll
    for (int nf = 0; nf < 16; ++nf){
        const float v0 = oacc[nf][0]*i0, v1 = oacc[nf][1]*i0;
        const float v2 = oacc[nf][2]*i1, v3 = oacc[nf][3]*i1;
        uint32_t h01, l01, h23, l23;
        packhl(v0, v1, h01, l01);
        packhl(v2, v3, h23, l23);
        const size_t o0 = (size_t)gr0*GD + cb + nf*8;
        const size_t o1 = (size_t)(gr0+8)*GD + cb + nf*8;
        *(uint32_t*)(g_attnh + o0) = h01;
        *(uint32_t*)(g_attnl + o0) = l01;
        *(uint32_t*)(g_attnh + o1) = h23;
        *(uint32_t*)(g_attnl + o1) = l23;
    }
}

// ---------------- launch ----------------
extern "C" void kernel_launch(void* const* d_in, const int* in_sizes, int n_in,
                              void* d_out, int out_size)
{
    const float* x    = (const float*)d_in[0];
    const float* Wqkv = (const float*)d_in[1];
    const float* Wo   = (const float*)d_in[2];
    float* out = (float*)d_out;

    cudaFuncSetAttribute(gemm_qkv_kernel, cudaFuncAttributeMaxDynamicSharedMemorySize, GEMM_SMEM);
    cudaFuncSetAttribute(gemm_out_kernel, cudaFuncAttributeMaxDynamicSharedMemorySize, GEMM_SMEM);
    cudaFuncSetAttribute(attn_mma_kernel, cudaFuncAttributeMaxDynamicSharedMemorySize, ATT_SMEM);

    unsigned long long *xh, *xl, *wqh, *wql, *woh, *wol;
    cudaGetSymbolAddress((void**)&xh,  g_xh);
    cudaGetSymbolAddress((void**)&xl,  g_xl);
    cudaGetSymbolAddress((void**)&wqh, g_wqkvh);
    cudaGetSymbolAddress((void**)&wql, g_wqkvl);
    cudaGetSymbolAddress((void**)&woh, g_woh);
    cudaGetSymbolAddress((void**)&wol, g_wol);

    const int nx  = GB*GS*GD/4;
    const int nwq = QKV_OUT*GD/4;
    const int nwo = GD*GD/4;
    cvt_pair_kernel<<<(nx +255)/256, 256>>>((const float4*)x,    xh,  xl,  nx);
    cvt_pair_kernel<<<(nwq+255)/256, 256>>>((const float4*)Wqkv, wqh, wql, nwq);
    cvt_pair_kernel<<<(nwo+255)/256, 256>>>((const float4*)Wo,   woh, wol, nwo);

    dim3 g1(QKV_OUT/128, (GB*GS)/128);
    gemm_qkv_kernel<<<g1, 256, GEMM_SMEM>>>();

    rope_kernel<<<GB*GS, 256>>>();

    const int nqk = GB*GS*QKSTRIDE/4;
    qkconv_kernel<<<(nqk+255)/256, 256>>>();
    dim3 gv(GS/32, GHD/32, GB*GKH);
    vconv_kernel<<<gv, dim3(32,8)>>>();

    dim3 ga(GS/128, GH, GB);
    attn_mma_kernel<<<ga, 256, ATT_SMEM>>>();

    dim3 g2(GD/128, (GB*GS)/128);
    gemm_out_kernel<<<g2, 256, GEMM_SMEM>>>(out);
}